// round 1
// baseline (speedup 1.0000x reference)
#include <cuda_runtime.h>
#include <cuda_bf16.h>
#include <math.h>

// Problem constants
#define Bsz   1024
#define Ssz   8
#define Hsz   16
#define DKsz  32
#define DVsz  32
#define Dsz   512
#define MTOT  (Bsz * Ssz)          // 8192 rows
#define OUT_ELEMS   ((size_t)MTOT * Dsz)          // 4194304
#define W_ELEMS     ((size_t)Bsz * Hsz * Ssz * Ssz) // 1048576

// Scratch (allocation-free rule: __device__ globals)
__device__ float g_q[MTOT * Dsz];
__device__ float g_k[MTOT * Dsz];
__device__ float g_v[MTOT * Dsz];
__device__ float g_ctx[MTOT * Dsz];
__device__ float g_lin[MTOT * Dsz];

// ---------------------------------------------------------------------------
// Generic GEMM: C[M=8192, 512] = A[8192,512] @ W[512,512]^T + bias (+ R)
// Block tile 64x64, K-tile 16, 256 threads, 4x4 per thread.
// ---------------------------------------------------------------------------
__global__ __launch_bounds__(256) void gemm_bias_res(
    const float* __restrict__ A, const float* __restrict__ W,
    const float* __restrict__ bias, const float* __restrict__ R,
    float* __restrict__ C)
{
    __shared__ float As[16][65];
    __shared__ float Bs[16][65];

    const int tid = threadIdx.x;
    const int bm  = blockIdx.y * 64;
    const int bn  = blockIdx.x * 64;
    const int tx  = tid & 15;        // 0..15 -> n
    const int ty  = tid >> 4;        // 0..15 -> m
    const int lrow = tid >> 2;       // 0..63
    const int lk   = (tid & 3) * 4;  // 0,4,8,12

    const float* Ap = A + (size_t)(bm + lrow) * Dsz + lk;
    const float* Wp = W + (size_t)(bn + lrow) * Dsz + lk;

    float acc[4][4] = {};

    for (int k0 = 0; k0 < Dsz; k0 += 16) {
        float4 av = *(const float4*)(Ap + k0);
        float4 wv = *(const float4*)(Wp + k0);
        __syncthreads();
        As[lk + 0][lrow] = av.x; As[lk + 1][lrow] = av.y;
        As[lk + 2][lrow] = av.z; As[lk + 3][lrow] = av.w;
        Bs[lk + 0][lrow] = wv.x; Bs[lk + 1][lrow] = wv.y;
        Bs[lk + 2][lrow] = wv.z; Bs[lk + 3][lrow] = wv.w;
        __syncthreads();
#pragma unroll
        for (int kk = 0; kk < 16; kk++) {
            float a0 = As[kk][ty * 4 + 0];
            float a1 = As[kk][ty * 4 + 1];
            float a2 = As[kk][ty * 4 + 2];
            float a3 = As[kk][ty * 4 + 3];
            float b0 = Bs[kk][tx * 4 + 0];
            float b1 = Bs[kk][tx * 4 + 1];
            float b2 = Bs[kk][tx * 4 + 2];
            float b3 = Bs[kk][tx * 4 + 3];
            acc[0][0] += a0 * b0; acc[0][1] += a0 * b1; acc[0][2] += a0 * b2; acc[0][3] += a0 * b3;
            acc[1][0] += a1 * b0; acc[1][1] += a1 * b1; acc[1][2] += a1 * b2; acc[1][3] += a1 * b3;
            acc[2][0] += a2 * b0; acc[2][1] += a2 * b1; acc[2][2] += a2 * b2; acc[2][3] += a2 * b3;
            acc[3][0] += a3 * b0; acc[3][1] += a3 * b1; acc[3][2] += a3 * b2; acc[3][3] += a3 * b3;
        }
    }

#pragma unroll
    for (int i = 0; i < 4; i++) {
        const int m = bm + ty * 4 + i;
#pragma unroll
        for (int j = 0; j < 4; j++) {
            const int n = bn + tx * 4 + j;
            float v = acc[i][j] + bias[n];
            if (R) v += R[(size_t)m * Dsz + n];
            C[(size_t)m * Dsz + n] = v;
        }
    }
}

// ---------------------------------------------------------------------------
// Attention per (b, h): scores -> mask -> softmax -> weights out, gated ctx.
// 256 threads: (s = tid>>5, d = tid&31).
// Mask test is bitwise-nonzero: works whether mask arrives as i32 0/1 or f32 0.0/1.0.
// ---------------------------------------------------------------------------
__global__ __launch_bounds__(256) void attn_kernel(
    const float* __restrict__ gq, const float* __restrict__ gk,
    const float* __restrict__ gv, const unsigned int* __restrict__ mask,
    const float* __restrict__ hyper, float* __restrict__ weights_out,
    float* __restrict__ ctx)
{
    const int b = blockIdx.x;
    const int h = blockIdx.y;
    const int tid = threadIdx.x;
    const int s = tid >> 5;
    const int d = tid & 31;

    __shared__ float qs[8][32], ks[8][32], vs[8][32];
    __shared__ float ws[8][8];

    const size_t rowbase = ((size_t)b * Ssz + s) * Dsz + (size_t)h * DKsz;
    qs[s][d] = gq[rowbase + d];
    ks[s][d] = gk[rowbase + d];
    vs[s][d] = gv[rowbase + d];
    __syncthreads();

    if (tid < 64) {
        const int i = tid >> 3, j = tid & 7;
        float acc = 0.f;
#pragma unroll
        for (int dd = 0; dd < 32; dd++) acc += qs[i][dd] * ks[j][dd];
        acc *= 0.17677669529663687f;   // 1/sqrt(32)
        if (mask[((size_t)b * Ssz + i) * Ssz + j] != 0u) acc = -1e9f;
        ws[i][j] = acc;
    }
    __syncthreads();

    if (tid < 8) {
        const int i = tid;
        float m = ws[i][0];
#pragma unroll
        for (int j = 1; j < 8; j++) m = fmaxf(m, ws[i][j]);
        float e[8];
        float sum = 0.f;
#pragma unroll
        for (int j = 0; j < 8; j++) { e[j] = expf(ws[i][j] - m); sum += e[j]; }
        const float inv = 1.f / sum;
#pragma unroll
        for (int j = 0; j < 8; j++) ws[i][j] = e[j] * inv;
    }
    __syncthreads();

    if (tid < 64) {
        const int i = tid >> 3, j = tid & 7;
        weights_out[(((size_t)b * Hsz + h) * Ssz + i) * Ssz + j] = ws[i][j];
    }

    float c = 0.f;
#pragma unroll
    for (int j = 0; j < 8; j++) c += ws[s][j] * vs[j][d];
    c *= hyper[(size_t)b * (Hsz * Ssz * DKsz) + ((size_t)h * Ssz + s) * DKsz + d];
    ctx[rowbase + d] = c;
}

// ---------------------------------------------------------------------------
// LayerNorm per row (eps=1e-5, population var). 128 threads, float4 each.
// ---------------------------------------------------------------------------
__global__ __launch_bounds__(128) void ln_kernel(
    const float* __restrict__ x, const float* __restrict__ gam,
    const float* __restrict__ bet, float* __restrict__ out)
{
    const int row = blockIdx.x;
    const int tid = threadIdx.x;
    const float4 v = ((const float4*)(x + (size_t)row * Dsz))[tid];

    float s  = v.x + v.y + v.z + v.w;
    float ss = v.x * v.x + v.y * v.y + v.z * v.z + v.w * v.w;
#pragma unroll
    for (int off = 16; off > 0; off >>= 1) {
        s  += __shfl_xor_sync(0xFFFFFFFFu, s,  off);
        ss += __shfl_xor_sync(0xFFFFFFFFu, ss, off);
    }
    __shared__ float sbuf[4], ssbuf[4];
    __shared__ float s_mu, s_rstd;
    if ((tid & 31) == 0) { sbuf[tid >> 5] = s; ssbuf[tid >> 5] = ss; }
    __syncthreads();
    if (tid == 0) {
        float ts = sbuf[0] + sbuf[1] + sbuf[2] + sbuf[3];
        float tss = ssbuf[0] + ssbuf[1] + ssbuf[2] + ssbuf[3];
        const float mu = ts * (1.f / Dsz);
        const float var = tss * (1.f / Dsz) - mu * mu;
        s_mu = mu;
        s_rstd = rsqrtf(var + 1e-5f);
    }
    __syncthreads();
    const float mu = s_mu, rstd = s_rstd;

    const float4 g4 = ((const float4*)gam)[tid];
    const float4 b4 = ((const float4*)bet)[tid];
    float4 o;
    o.x = (v.x - mu) * rstd * g4.x + b4.x;
    o.y = (v.y - mu) * rstd * g4.y + b4.y;
    o.z = (v.z - mu) * rstd * g4.z + b4.z;
    o.w = (v.w - mu) * rstd * g4.w + b4.w;
    ((float4*)(out + (size_t)row * Dsz))[tid] = o;
}

// ---------------------------------------------------------------------------
extern "C" void kernel_launch(void* const* d_in, const int* in_sizes, int n_in,
                              void* d_out, int out_size)
{
    const float* Q     = (const float*)d_in[0];
    const float* K     = (const float*)d_in[1];
    const float* V     = (const float*)d_in[2];
    const unsigned int* mask = (const unsigned int*)d_in[3];
    const float* hyper = (const float*)d_in[4];
    const float* Wq    = (const float*)d_in[5];
    const float* bq    = (const float*)d_in[6];
    const float* Wk    = (const float*)d_in[7];
    const float* bk    = (const float*)d_in[8];
    const float* Wv    = (const float*)d_in[9];
    const float* bv    = (const float*)d_in[10];
    const float* Wo    = (const float*)d_in[11];
    const float* bo    = (const float*)d_in[12];
    const float* ln_g  = (const float*)d_in[13];
    const float* ln_b  = (const float*)d_in[14];

    float* outp = (float*)d_out;              // [B,S,D]
    float* wout = outp + OUT_ELEMS;           // [B,H,S,S]

    float *pq, *pk, *pv, *pctx, *plin;
    cudaGetSymbolAddress((void**)&pq,   g_q);
    cudaGetSymbolAddress((void**)&pk,   g_k);
    cudaGetSymbolAddress((void**)&pv,   g_v);
    cudaGetSymbolAddress((void**)&pctx, g_ctx);
    cudaGetSymbolAddress((void**)&plin, g_lin);

    dim3 ggrid(Dsz / 64, MTOT / 64);   // (8, 128)

    gemm_bias_res<<<ggrid, 256>>>(Q, Wq, bq, nullptr, pq);
    gemm_bias_res<<<ggrid, 256>>>(K, Wk, bk, nullptr, pk);
    gemm_bias_res<<<ggrid, 256>>>(V, Wv, bv, nullptr, pv);

    dim3 agrid(Bsz, Hsz);
    attn_kernel<<<agrid, 256>>>(pq, pk, pv, mask, hyper, wout, pctx);

    gemm_bias_res<<<ggrid, 256>>>(pctx, Wo, bo, Q, plin);

    ln_kernel<<<MTOT, 128>>>(plin, ln_g, ln_b, outp);
}

// round 5
// speedup vs baseline: 2.5507x; 2.5507x over previous
#include <cuda_runtime.h>
#include <cuda_bf16.h>
#include <cstdint>
#include <math.h>

// Problem constants
#define Bsz   1024
#define Ssz   8
#define Hsz   16
#define DKsz  32
#define Dsz   512
#define MTOT  (Bsz * Ssz)                      // 8192
#define OUT_ELEMS ((size_t)MTOT * Dsz)         // 4194304

// ---------------------------------------------------------------------------
// Scratch (__device__ globals — allocation-free rule)
// ---------------------------------------------------------------------------
__device__ float g_q[MTOT * Dsz];
__device__ float g_k[MTOT * Dsz];
__device__ float g_v[MTOT * Dsz];
__device__ float g_ctx[MTOT * Dsz];
__device__ float g_lin[MTOT * Dsz];

// ---------------------------------------------------------------------------
// PTX wrappers (plain sm_100-compatible: ldmatrix + mma.sync, no tcgen05)
// ---------------------------------------------------------------------------
__device__ __forceinline__ uint32_t smem_u32(const void* p) {
    uint32_t a;
    asm("{ .reg .u64 t; cvta.to.shared.u64 t, %1; cvt.u32.u64 %0, t; }"
        : "=r"(a) : "l"(p));
    return a;
}

#define LDSM4(r, addr) \
    asm volatile("ldmatrix.sync.aligned.m8n8.x4.shared.b16 {%0,%1,%2,%3}, [%4];" \
        : "=r"((r)[0]), "=r"((r)[1]), "=r"((r)[2]), "=r"((r)[3]) : "r"(addr))
#define LDSM2(r, addr) \
    asm volatile("ldmatrix.sync.aligned.m8n8.x2.shared.b16 {%0,%1}, [%2];" \
        : "=r"((r)[0]), "=r"((r)[1]) : "r"(addr))
#define MMA16816(d, a, b) \
    asm volatile("mma.sync.aligned.m16n8k16.row.col.f32.bf16.bf16.f32 " \
        "{%0,%1,%2,%3}, {%4,%5,%6,%7}, {%8,%9}, {%0,%1,%2,%3};" \
        : "+f"((d)[0]), "+f"((d)[1]), "+f"((d)[2]), "+f"((d)[3]) \
        : "r"((a)[0]), "r"((a)[1]), "r"((a)[2]), "r"((a)[3]), "r"((b)[0]), "r"((b)[1]))

__device__ __forceinline__ uint32_t pack_bf2(__nv_bfloat16 x, __nv_bfloat16 y) {
    __nv_bfloat162 p(x, y);
    return *reinterpret_cast<uint32_t*>(&p);
}

// ---------------------------------------------------------------------------
// GEMM: C[8192,512] = A[8192,512] @ W[512,512]^T + bias (+R)
// fp32 inputs converted in-register to bf16 (hi, lo) splits; 3-term MMA:
//   Ahi*Whi + Alo*Whi + Ahi*Wlo   (fp32 register accumulators)
// CTA tile 128(M) x 64(N), K-chunk 32, 256 threads (8 warps, warp tile 32x32).
// Single smem stage + register prefetch of the next K-chunk.
// Smem rows padded to 80B -> conflict-free ldmatrix (bank start = 20*r % 32).
// ---------------------------------------------------------------------------
#define BM 128
#define BN 64
#define BK 32
#define RSTRIDE 80
#define S_AHI 0
#define S_ALO 10240
#define S_BHI 20480
#define S_BLO 25600
#define SMEM_SZ 30720

__global__ __launch_bounds__(256) void gemm_mma(
    const float* __restrict__ A, const float* __restrict__ W,
    const float* __restrict__ bias, const float* __restrict__ R,
    float* __restrict__ C)
{
    __shared__ char smbuf[SMEM_SZ];
    const uint32_t sbase = smem_u32(smbuf);
    const int tid = threadIdx.x;
    const int lane = tid & 31;
    const int wid = tid >> 5;
    const int wm = wid >> 1;          // 0..3 (M)
    const int wn = wid & 1;           // 0..1 (N)
    const int bm = blockIdx.y * BM;
    const int bn = blockIdx.x * BN;

    const uint4* A4 = (const uint4*)A;   // row stride 128 uint4
    const uint4* W4 = (const uint4*)W;

    // ldmatrix source offsets (relative; add S_* + kstep*32)
    uint32_t aoff[2], boff[4];
#pragma unroll
    for (int im = 0; im < 2; im++)
        aoff[im] = (uint32_t)((wm * 32 + im * 16 + (lane & 15)) * RSTRIDE +
                              ((lane >> 4) & 1) * 16);
#pragma unroll
    for (int in = 0; in < 4; in++)
        boff[in] = (uint32_t)((wn * 32 + in * 8 + (lane & 7)) * RSTRIDE +
                              ((lane >> 3) & 1) * 16);

    float acc[2][4][4];
#pragma unroll
    for (int im = 0; im < 2; im++)
#pragma unroll
        for (int in = 0; in < 4; in++)
#pragma unroll
            for (int q = 0; q < 4; q++) acc[im][in][q] = 0.f;

    // per-thread load slots: 6 x uint4 per K-chunk (A: 1024 items, B: 512)
    uint4 pre[6];

    auto prefetch = [&](int kc) {
#pragma unroll
        for (int j = 0; j < 6; j++) {
            int u = tid + j * 256;
            if (u < 1024)
                pre[j] = A4[(size_t)(bm + (u >> 3)) * 128 + kc * 8 + (u & 7)];
            else {
                int v = u - 1024;
                pre[j] = W4[(size_t)(bn + (v >> 3)) * 128 + kc * 8 + (v & 7)];
            }
        }
    };

    auto store_stage = [&]() {
#pragma unroll
        for (int j = 0; j < 6; j++) {
            int u = tid + j * 256;
            int off, hbase, lbase;
            if (u < 1024) {
                off = (u >> 3) * RSTRIDE + (u & 7) * 8;
                hbase = S_AHI; lbase = S_ALO;
            } else {
                int v = u - 1024;
                off = (v >> 3) * RSTRIDE + (v & 7) * 8;
                hbase = S_BHI; lbase = S_BLO;
            }
            float4 f = *reinterpret_cast<float4*>(&pre[j]);
            __nv_bfloat16 h0 = __float2bfloat16_rn(f.x);
            __nv_bfloat16 h1 = __float2bfloat16_rn(f.y);
            __nv_bfloat16 h2 = __float2bfloat16_rn(f.z);
            __nv_bfloat16 h3 = __float2bfloat16_rn(f.w);
            uint2 hv = { pack_bf2(h0, h1), pack_bf2(h2, h3) };
            uint2 lv = { pack_bf2(__float2bfloat16_rn(f.x - __bfloat162float(h0)),
                                  __float2bfloat16_rn(f.y - __bfloat162float(h1))),
                         pack_bf2(__float2bfloat16_rn(f.z - __bfloat162float(h2)),
                                  __float2bfloat16_rn(f.w - __bfloat162float(h3))) };
            *reinterpret_cast<uint2*>(smbuf + hbase + off) = hv;
            *reinterpret_cast<uint2*>(smbuf + lbase + off) = lv;
        }
    };

    prefetch(0);
    for (int kc = 0; kc < 16; kc++) {
        __syncthreads();
        store_stage();
        __syncthreads();
        if (kc < 15) prefetch(kc + 1);   // LDG latency overlapped with compute

#pragma unroll
        for (int ks = 0; ks < 2; ks++) {
            const uint32_t kb = ks * 32;
            uint32_t ah[2][4], bh[4][2], tmpA[2][4], tmpB[4][2];
#pragma unroll
            for (int im = 0; im < 2; im++) LDSM4(ah[im], sbase + S_AHI + aoff[im] + kb);
#pragma unroll
            for (int in = 0; in < 4; in++) LDSM2(bh[in], sbase + S_BHI + boff[in] + kb);
#pragma unroll
            for (int im = 0; im < 2; im++)
#pragma unroll
                for (int in = 0; in < 4; in++) MMA16816(acc[im][in], ah[im], bh[in]);
            // lo(A) * hi(B)
#pragma unroll
            for (int im = 0; im < 2; im++) LDSM4(tmpA[im], sbase + S_ALO + aoff[im] + kb);
#pragma unroll
            for (int im = 0; im < 2; im++)
#pragma unroll
                for (int in = 0; in < 4; in++) MMA16816(acc[im][in], tmpA[im], bh[in]);
            // hi(A) * lo(B)
#pragma unroll
            for (int in = 0; in < 4; in++) LDSM2(tmpB[in], sbase + S_BLO + boff[in] + kb);
#pragma unroll
            for (int im = 0; im < 2; im++)
#pragma unroll
                for (int in = 0; in < 4; in++) MMA16816(acc[im][in], ah[im], tmpB[in]);
        }
    }

    // Epilogue: fragment d0..d3 -> C[g][2t],C[g][2t+1],C[g+8][2t],C[g+8][2t+1]
    const int g = lane >> 2, tg = lane & 3;
#pragma unroll
    for (int im = 0; im < 2; im++) {
#pragma unroll
        for (int in = 0; in < 4; in++) {
            const int row = bm + wm * 32 + im * 16 + g;
            const int col = bn + wn * 32 + in * 8 + tg * 2;
            const float b0 = bias[col], b1 = bias[col + 1];
            float2 v0 = { acc[im][in][0] + b0, acc[im][in][1] + b1 };
            float2 v1 = { acc[im][in][2] + b0, acc[im][in][3] + b1 };
            const size_t o0 = (size_t)row * Dsz + col;
            const size_t o1 = (size_t)(row + 8) * Dsz + col;
            if (R) {
                v0.x += R[o0];     v0.y += R[o0 + 1];
                v1.x += R[o1];     v1.y += R[o1 + 1];
            }
            *reinterpret_cast<float2*>(&C[o0]) = v0;
            *reinterpret_cast<float2*>(&C[o1]) = v1;
        }
    }
}

// ---------------------------------------------------------------------------
// Attention: one warp per (b, h, row). Shuffle-reduced dots, register softmax.
// ---------------------------------------------------------------------------
__global__ __launch_bounds__(256) void attn2(
    const float* __restrict__ gq, const float* __restrict__ gk,
    const float* __restrict__ gv, const unsigned int* __restrict__ mask,
    const float* __restrict__ hyper, float* __restrict__ wout,
    float* __restrict__ ctx)
{
    const int b = blockIdx.x;
    const int h = blockIdx.y;
    const int tid = threadIdx.x;
    const int i = tid >> 5;       // row
    const int lane = tid & 31;    // d

    __shared__ float ks[8][32], vs[8][32];

    const size_t rowbase = ((size_t)b * Ssz + i) * Dsz + (size_t)h * DKsz;
    ks[i][lane] = gk[rowbase + lane];
    vs[i][lane] = gv[rowbase + lane];
    const float qv = gq[rowbase + lane];
    const unsigned int mv = mask[(size_t)b * 64 + i * 8 + (lane & 7)];
    __syncthreads();

    float sc[8];
#pragma unroll
    for (int j = 0; j < 8; j++) {
        float p = qv * ks[j][lane];
        p += __shfl_xor_sync(0xFFFFFFFFu, p, 16);
        p += __shfl_xor_sync(0xFFFFFFFFu, p, 8);
        p += __shfl_xor_sync(0xFFFFFFFFu, p, 4);
        p += __shfl_xor_sync(0xFFFFFFFFu, p, 2);
        p += __shfl_xor_sync(0xFFFFFFFFu, p, 1);
        const unsigned int mj = __shfl_sync(0xFFFFFFFFu, mv, j);
        sc[j] = (mj != 0u) ? -1e9f : p * 0.17677669529663687f;
    }

    float m = sc[0];
#pragma unroll
    for (int j = 1; j < 8; j++) m = fmaxf(m, sc[j]);
    float sum = 0.f;
#pragma unroll
    for (int j = 0; j < 8; j++) { sc[j] = __expf(sc[j] - m); sum += sc[j]; }
    const float inv = 1.f / sum;
#pragma unroll
    for (int j = 0; j < 8; j++) sc[j] *= inv;

    if (lane < 8)
        wout[(((size_t)b * Hsz + h) * Ssz + i) * Ssz + lane] = sc[lane];

    float c = 0.f;
#pragma unroll
    for (int j = 0; j < 8; j++) c += sc[j] * vs[j][lane];
    c *= hyper[(size_t)b * 4096 + h * 256 + i * 32 + lane];
    ctx[rowbase + lane] = c;
}

// ---------------------------------------------------------------------------
// LayerNorm per row (eps=1e-5). 128 threads, float4 each.
// ---------------------------------------------------------------------------
__global__ __launch_bounds__(128) void ln_kernel(
    const float* __restrict__ x, const float* __restrict__ gam,
    const float* __restrict__ bet, float* __restrict__ out)
{
    const int row = blockIdx.x;
    const int tid = threadIdx.x;
    const float4 v = ((const float4*)(x + (size_t)row * Dsz))[tid];

    float s  = v.x + v.y + v.z + v.w;
    float ss = v.x * v.x + v.y * v.y + v.z * v.z + v.w * v.w;
#pragma unroll
    for (int off = 16; off > 0; off >>= 1) {
        s  += __shfl_xor_sync(0xFFFFFFFFu, s,  off);
        ss += __shfl_xor_sync(0xFFFFFFFFu, ss, off);
    }
    __shared__ float sbuf[4], ssbuf[4];
    __shared__ float s_mu, s_rstd;
    if ((tid & 31) == 0) { sbuf[tid >> 5] = s; ssbuf[tid >> 5] = ss; }
    __syncthreads();
    if (tid == 0) {
        const float ts  = sbuf[0] + sbuf[1] + sbuf[2] + sbuf[3];
        const float tss = ssbuf[0] + ssbuf[1] + ssbuf[2] + ssbuf[3];
        const float mu  = ts * (1.f / Dsz);
        const float var = tss * (1.f / Dsz) - mu * mu;
        s_mu = mu;
        s_rstd = rsqrtf(var + 1e-5f);
    }
    __syncthreads();
    const float mu = s_mu, rstd = s_rstd;

    const float4 g4 = ((const float4*)gam)[tid];
    const float4 b4 = ((const float4*)bet)[tid];
    float4 o;
    o.x = (v.x - mu) * rstd * g4.x + b4.x;
    o.y = (v.y - mu) * rstd * g4.y + b4.y;
    o.z = (v.z - mu) * rstd * g4.z + b4.z;
    o.w = (v.w - mu) * rstd * g4.w + b4.w;
    ((float4*)(out + (size_t)row * Dsz))[tid] = o;
}

// ---------------------------------------------------------------------------
extern "C" void kernel_launch(void* const* d_in, const int* in_sizes, int n_in,
                              void* d_out, int out_size)
{
    const float* Q     = (const float*)d_in[0];
    const float* K     = (const float*)d_in[1];
    const float* V     = (const float*)d_in[2];
    const unsigned int* mask = (const unsigned int*)d_in[3];
    const float* hyper = (const float*)d_in[4];
    const float* Wq    = (const float*)d_in[5];
    const float* bq    = (const float*)d_in[6];
    const float* Wk    = (const float*)d_in[7];
    const float* bk    = (const float*)d_in[8];
    const float* Wv    = (const float*)d_in[9];
    const float* bv    = (const float*)d_in[10];
    const float* Wo    = (const float*)d_in[11];
    const float* bo    = (const float*)d_in[12];
    const float* ln_g  = (const float*)d_in[13];
    const float* ln_b  = (const float*)d_in[14];

    float* outp = (float*)d_out;
    float* wout = outp + OUT_ELEMS;

    float *pq, *pk, *pv, *pctx, *plin;
    cudaGetSymbolAddress((void**)&pq,   g_q);
    cudaGetSymbolAddress((void**)&pk,   g_k);
    cudaGetSymbolAddress((void**)&pv,   g_v);
    cudaGetSymbolAddress((void**)&pctx, g_ctx);
    cudaGetSymbolAddress((void**)&plin, g_lin);

    dim3 ggrid(Dsz / BN, MTOT / BM);   // (8, 64)

    gemm_mma<<<ggrid, 256>>>(Q, Wq, bq, nullptr, pq);
    gemm_mma<<<ggrid, 256>>>(K, Wk, bk, nullptr, pk);
    gemm_mma<<<ggrid, 256>>>(V, Wv, bv, nullptr, pv);

    dim3 agrid(Bsz, Hsz);
    attn2<<<agrid, 256>>>(pq, pk, pv, mask, hyper, wout, pctx);

    gemm_mma<<<ggrid, 256>>>(pctx, Wo, bo, Q, plin);

    ln_kernel<<<MTOT, 128>>>(plin, ln_g, ln_b, outp);
}

// round 6
// speedup vs baseline: 2.8681x; 1.1244x over previous
#include <cuda_runtime.h>
#include <cuda_bf16.h>
#include <cstdint>
#include <math.h>

// Problem constants
#define Bsz   1024
#define Ssz   8
#define Hsz   16
#define DKsz  32
#define Dsz   512
#define MTOT  (Bsz * Ssz)                      // 8192
#define OUT_ELEMS ((size_t)MTOT * Dsz)         // 4194304

// ---------------------------------------------------------------------------
// Scratch (__device__ globals — allocation-free rule)
// ---------------------------------------------------------------------------
__device__ float g_q[MTOT * Dsz];
__device__ float g_k[MTOT * Dsz];
__device__ float g_v[MTOT * Dsz];
__device__ float g_ctx[MTOT * Dsz];
__device__ float g_lin[MTOT * Dsz];

// ---------------------------------------------------------------------------
// PTX wrappers (plain sm_100-compatible: ldmatrix + mma.sync, no tcgen05)
// ---------------------------------------------------------------------------
__device__ __forceinline__ uint32_t smem_u32(const void* p) {
    uint32_t a;
    asm("{ .reg .u64 t; cvta.to.shared.u64 t, %1; cvt.u32.u64 %0, t; }"
        : "=r"(a) : "l"(p));
    return a;
}

#define LDSM4(r, addr) \
    asm volatile("ldmatrix.sync.aligned.m8n8.x4.shared.b16 {%0,%1,%2,%3}, [%4];" \
        : "=r"((r)[0]), "=r"((r)[1]), "=r"((r)[2]), "=r"((r)[3]) : "r"(addr))
#define LDSM2(r, addr) \
    asm volatile("ldmatrix.sync.aligned.m8n8.x2.shared.b16 {%0,%1}, [%2];" \
        : "=r"((r)[0]), "=r"((r)[1]) : "r"(addr))
#define MMA16816(d, a, b) \
    asm volatile("mma.sync.aligned.m16n8k16.row.col.f32.bf16.bf16.f32 " \
        "{%0,%1,%2,%3}, {%4,%5,%6,%7}, {%8,%9}, {%0,%1,%2,%3};" \
        : "+f"((d)[0]), "+f"((d)[1]), "+f"((d)[2]), "+f"((d)[3]) \
        : "r"((a)[0]), "r"((a)[1]), "r"((a)[2]), "r"((a)[3]), "r"((b)[0]), "r"((b)[1]))

// ---------------------------------------------------------------------------
// GEMM: C[8192,512] = A[8192,512] @ W[512,512]^T + bias (+R)
// fp32 inputs converted in-register to bf16 (hi, lo) splits; 3-term MMA:
//   Ahi*Whi + Alo*Whi + Ahi*Wlo   (fp32 register accumulators)
// CTA tile 128(M) x 128(N), K-chunk 32, 512 threads (16 warps 4x4, warp 32x32).
// Double-buffered bf16 smem (ping-pong), register prefetch one chunk ahead.
// Smem rows padded to 80B -> conflict-free ldmatrix (bank start = 20*r % 32).
// ---------------------------------------------------------------------------
#define BM 128
#define BN 128
#define RSTRIDE 80
#define S_AHI 0
#define S_ALO 10240
#define S_BHI 20480
#define S_BLO 30720
#define STAGE_SZ 40960
#define SMEM_SZ (2 * STAGE_SZ)   // 80 KB dynamic

__global__ __launch_bounds__(512) void gemm_mma(
    const float* __restrict__ A, const float* __restrict__ W,
    const float* __restrict__ bias, const float* __restrict__ R,
    float* __restrict__ C)
{
    extern __shared__ char smbuf[];
    const uint32_t sbase = smem_u32(smbuf);
    const int tid = threadIdx.x;
    const int lane = tid & 31;
    const int wid = tid >> 5;
    const int wm = wid >> 2;          // 0..3 (M)
    const int wn = wid & 3;           // 0..3 (N)
    const int bm = blockIdx.y * BM;
    const int bn = blockIdx.x * BN;

    const uint4* A4 = (const uint4*)A;   // row stride 128 uint4
    const uint4* W4 = (const uint4*)W;

    // ldmatrix source offsets (relative; add stage base + S_* + kstep*32)
    uint32_t aoff[2], boff[4];
#pragma unroll
    for (int im = 0; im < 2; im++)
        aoff[im] = (uint32_t)((wm * 32 + im * 16 + (lane & 15)) * RSTRIDE +
                              ((lane >> 4) & 1) * 16);
#pragma unroll
    for (int in = 0; in < 4; in++)
        boff[in] = (uint32_t)((wn * 32 + in * 8 + (lane & 7)) * RSTRIDE +
                              ((lane >> 3) & 1) * 16);

    float acc[2][4][4];
#pragma unroll
    for (int im = 0; im < 2; im++)
#pragma unroll
        for (int in = 0; in < 4; in++)
#pragma unroll
            for (int q = 0; q < 4; q++) acc[im][in][q] = 0.f;

    // per-thread load slots: 4 x uint4 per K-chunk (A: 1024 items, B: 1024)
    uint4 pre[4];

    auto prefetch = [&](int kc) {
#pragma unroll
        for (int j = 0; j < 4; j++) {
            int u = tid + j * 512;
            if (u < 1024)
                pre[j] = A4[(size_t)(bm + (u >> 3)) * 128 + kc * 8 + (u & 7)];
            else {
                int v = u - 1024;
                pre[j] = W4[(size_t)(bn + (v >> 3)) * 128 + kc * 8 + (v & 7)];
            }
        }
    };

    auto store_stage = [&](int buf) {
        char* bp = smbuf + buf * STAGE_SZ;
#pragma unroll
        for (int j = 0; j < 4; j++) {
            int u = tid + j * 512;
            int off, hbase, lbase;
            if (u < 1024) {
                off = (u >> 3) * RSTRIDE + (u & 7) * 8;
                hbase = S_AHI; lbase = S_ALO;
            } else {
                int v = u - 1024;
                off = (v >> 3) * RSTRIDE + (v & 7) * 8;
                hbase = S_BHI; lbase = S_BLO;
            }
            float4 f = *reinterpret_cast<float4*>(&pre[j]);
            __nv_bfloat162 h01 = __float22bfloat162_rn(make_float2(f.x, f.y));
            __nv_bfloat162 h23 = __float22bfloat162_rn(make_float2(f.z, f.w));
            float2 fh01 = __bfloat1622float2(h01);
            float2 fh23 = __bfloat1622float2(h23);
            __nv_bfloat162 l01 = __float22bfloat162_rn(make_float2(f.x - fh01.x, f.y - fh01.y));
            __nv_bfloat162 l23 = __float22bfloat162_rn(make_float2(f.z - fh23.x, f.w - fh23.y));
            uint2 hv = { *reinterpret_cast<uint32_t*>(&h01), *reinterpret_cast<uint32_t*>(&h23) };
            uint2 lv = { *reinterpret_cast<uint32_t*>(&l01), *reinterpret_cast<uint32_t*>(&l23) };
            *reinterpret_cast<uint2*>(bp + hbase + off) = hv;
            *reinterpret_cast<uint2*>(bp + lbase + off) = lv;
        }
    };

    // Pipeline prologue: stage 0 resident, chunk 1 in flight.
    prefetch(0);
    store_stage(0);
    prefetch(1);
    __syncthreads();

    for (int kc = 0; kc < 16; kc++) {
        const uint32_t sb = sbase + (kc & 1) * STAGE_SZ;

        // compute on current stage
#pragma unroll
        for (int ks = 0; ks < 2; ks++) {
            const uint32_t kb = ks * 32;
            uint32_t ah[2][4], bh[4][2], al[2][4], bl[4][2];
#pragma unroll
            for (int im = 0; im < 2; im++) LDSM4(ah[im], sb + S_AHI + aoff[im] + kb);
#pragma unroll
            for (int in = 0; in < 4; in++) LDSM2(bh[in], sb + S_BHI + boff[in] + kb);
#pragma unroll
            for (int im = 0; im < 2; im++)
#pragma unroll
                for (int in = 0; in < 4; in++) MMA16816(acc[im][in], ah[im], bh[in]);
#pragma unroll
            for (int im = 0; im < 2; im++) LDSM4(al[im], sb + S_ALO + aoff[im] + kb);
#pragma unroll
            for (int im = 0; im < 2; im++)
#pragma unroll
                for (int in = 0; in < 4; in++) MMA16816(acc[im][in], al[im], bh[in]);
#pragma unroll
            for (int in = 0; in < 4; in++) LDSM2(bl[in], sb + S_BLO + boff[in] + kb);
#pragma unroll
            for (int im = 0; im < 2; im++)
#pragma unroll
                for (int in = 0; in < 4; in++) MMA16816(acc[im][in], ah[im], bl[in]);
        }

        if (kc < 15) {
            store_stage((kc + 1) & 1);      // consumes pre (chunk kc+1)
            if (kc < 14) prefetch(kc + 2);  // refill pre; lands during next compute
        }
        __syncthreads();
    }

    // Epilogue: fragment d0..d3 -> C[g][2t],C[g][2t+1],C[g+8][2t],C[g+8][2t+1]
    const int g = lane >> 2, tg = lane & 3;
#pragma unroll
    for (int im = 0; im < 2; im++) {
#pragma unroll
        for (int in = 0; in < 4; in++) {
            const int row = bm + wm * 32 + im * 16 + g;
            const int col = bn + wn * 32 + in * 8 + tg * 2;
            const float b0 = bias[col], b1 = bias[col + 1];
            float2 v0 = { acc[im][in][0] + b0, acc[im][in][1] + b1 };
            float2 v1 = { acc[im][in][2] + b0, acc[im][in][3] + b1 };
            const size_t o0 = (size_t)row * Dsz + col;
            const size_t o1 = (size_t)(row + 8) * Dsz + col;
            if (R) {
                v0.x += R[o0];     v0.y += R[o0 + 1];
                v1.x += R[o1];     v1.y += R[o1 + 1];
            }
            *reinterpret_cast<float2*>(&C[o0]) = v0;
            *reinterpret_cast<float2*>(&C[o1]) = v1;
        }
    }
}

// ---------------------------------------------------------------------------
// Attention: one warp per (b, h, row). Shuffle-reduced dots, register softmax.
// ---------------------------------------------------------------------------
__global__ __launch_bounds__(256) void attn2(
    const float* __restrict__ gq, const float* __restrict__ gk,
    const float* __restrict__ gv, const unsigned int* __restrict__ mask,
    const float* __restrict__ hyper, float* __restrict__ wout,
    float* __restrict__ ctx)
{
    const int b = blockIdx.x;
    const int h = blockIdx.y;
    const int tid = threadIdx.x;
    const int i = tid >> 5;       // row
    const int lane = tid & 31;    // d

    __shared__ float ks[8][32], vs[8][32];

    const size_t rowbase = ((size_t)b * Ssz + i) * Dsz + (size_t)h * DKsz;
    ks[i][lane] = gk[rowbase + lane];
    vs[i][lane] = gv[rowbase + lane];
    const float qv = gq[rowbase + lane];
    const unsigned int mv = mask[(size_t)b * 64 + i * 8 + (lane & 7)];
    __syncthreads();

    float sc[8];
#pragma unroll
    for (int j = 0; j < 8; j++) {
        float p = qv * ks[j][lane];
        p += __shfl_xor_sync(0xFFFFFFFFu, p, 16);
        p += __shfl_xor_sync(0xFFFFFFFFu, p, 8);
        p += __shfl_xor_sync(0xFFFFFFFFu, p, 4);
        p += __shfl_xor_sync(0xFFFFFFFFu, p, 2);
        p += __shfl_xor_sync(0xFFFFFFFFu, p, 1);
        const unsigned int mj = __shfl_sync(0xFFFFFFFFu, mv, j);
        sc[j] = (mj != 0u) ? -1e9f : p * 0.17677669529663687f;
    }

    float m = sc[0];
#pragma unroll
    for (int j = 1; j < 8; j++) m = fmaxf(m, sc[j]);
    float sum = 0.f;
#pragma unroll
    for (int j = 0; j < 8; j++) { sc[j] = __expf(sc[j] - m); sum += sc[j]; }
    const float inv = 1.f / sum;
#pragma unroll
    for (int j = 0; j < 8; j++) sc[j] *= inv;

    if (lane < 8)
        wout[(((size_t)b * Hsz + h) * Ssz + i) * Ssz + lane] = sc[lane];

    float c = 0.f;
#pragma unroll
    for (int j = 0; j < 8; j++) c += sc[j] * vs[j][lane];
    c *= hyper[(size_t)b * 4096 + h * 256 + i * 32 + lane];
    ctx[rowbase + lane] = c;
}

// ---------------------------------------------------------------------------
// LayerNorm per row (eps=1e-5). 128 threads, float4 each.
// ---------------------------------------------------------------------------
__global__ __launch_bounds__(128) void ln_kernel(
    const float* __restrict__ x, const float* __restrict__ gam,
    const float* __restrict__ bet, float* __restrict__ out)
{
    const int row = blockIdx.x;
    const int tid = threadIdx.x;
    const float4 v = ((const float4*)(x + (size_t)row * Dsz))[tid];

    float s  = v.x + v.y + v.z + v.w;
    float ss = v.x * v.x + v.y * v.y + v.z * v.z + v.w * v.w;
#pragma unroll
    for (int off = 16; off > 0; off >>= 1) {
        s  += __shfl_xor_sync(0xFFFFFFFFu, s,  off);
        ss += __shfl_xor_sync(0xFFFFFFFFu, ss, off);
    }
    __shared__ float sbuf[4], ssbuf[4];
    __shared__ float s_mu, s_rstd;
    if ((tid & 31) == 0) { sbuf[tid >> 5] = s; ssbuf[tid >> 5] = ss; }
    __syncthreads();
    if (tid == 0) {
        const float ts  = sbuf[0] + sbuf[1] + sbuf[2] + sbuf[3];
        const float tss = ssbuf[0] + ssbuf[1] + ssbuf[2] + ssbuf[3];
        const float mu  = ts * (1.f / Dsz);
        const float var = tss * (1.f / Dsz) - mu * mu;
        s_mu = mu;
        s_rstd = rsqrtf(var + 1e-5f);
    }
    __syncthreads();
    const float mu = s_mu, rstd = s_rstd;

    const float4 g4 = ((const float4*)gam)[tid];
    const float4 b4 = ((const float4*)bet)[tid];
    float4 o;
    o.x = (v.x - mu) * rstd * g4.x + b4.x;
    o.y = (v.y - mu) * rstd * g4.y + b4.y;
    o.z = (v.z - mu) * rstd * g4.z + b4.z;
    o.w = (v.w - mu) * rstd * g4.w + b4.w;
    ((float4*)(out + (size_t)row * Dsz))[tid] = o;
}

// ---------------------------------------------------------------------------
extern "C" void kernel_launch(void* const* d_in, const int* in_sizes, int n_in,
                              void* d_out, int out_size)
{
    const float* Q     = (const float*)d_in[0];
    const float* K     = (const float*)d_in[1];
    const float* V     = (const float*)d_in[2];
    const unsigned int* mask = (const unsigned int*)d_in[3];
    const float* hyper = (const float*)d_in[4];
    const float* Wq    = (const float*)d_in[5];
    const float* bq    = (const float*)d_in[6];
    const float* Wk    = (const float*)d_in[7];
    const float* bk    = (const float*)d_in[8];
    const float* Wv    = (const float*)d_in[9];
    const float* bv    = (const float*)d_in[10];
    const float* Wo    = (const float*)d_in[11];
    const float* bo    = (const float*)d_in[12];
    const float* ln_g  = (const float*)d_in[13];
    const float* ln_b  = (const float*)d_in[14];

    float* outp = (float*)d_out;
    float* wout = outp + OUT_ELEMS;

    float *pq, *pk, *pv, *pctx, *plin;
    cudaGetSymbolAddress((void**)&pq,   g_q);
    cudaGetSymbolAddress((void**)&pk,   g_k);
    cudaGetSymbolAddress((void**)&pv,   g_v);
    cudaGetSymbolAddress((void**)&pctx, g_ctx);
    cudaGetSymbolAddress((void**)&plin, g_lin);

    cudaFuncSetAttribute(gemm_mma, cudaFuncAttributeMaxDynamicSharedMemorySize, SMEM_SZ);

    dim3 ggrid(Dsz / BN, MTOT / BM);   // (4, 64) = 256 CTAs

    gemm_mma<<<ggrid, 512, SMEM_SZ>>>(Q, Wq, bq, nullptr, pq);
    gemm_mma<<<ggrid, 512, SMEM_SZ>>>(K, Wk, bk, nullptr, pk);
    gemm_mma<<<ggrid, 512, SMEM_SZ>>>(V, Wv, bv, nullptr, pv);

    dim3 agrid(Bsz, Hsz);
    attn2<<<agrid, 256>>>(pq, pk, pv, mask, hyper, wout, pctx);

    gemm_mma<<<ggrid, 512, SMEM_SZ>>>(pctx, Wo, bo, Q, plin);

    ln_kernel<<<MTOT, 128>>>(plin, ln_g, ln_b, outp);
}

// round 8
// speedup vs baseline: 3.4483x; 1.2023x over previous
#include <cuda_runtime.h>
#include <cuda_fp16.h>
#include <cstdint>
#include <math.h>

// Problem constants
#define Bsz   1024
#define Ssz   8
#define Hsz   16
#define DKsz  32
#define Dsz   512
#define MTOT  (Bsz * Ssz)                      // 8192
#define OUT_ELEMS ((size_t)MTOT * Dsz)         // 4194304

// ---------------------------------------------------------------------------
// Scratch (__device__ globals — allocation-free rule)
// ---------------------------------------------------------------------------
__device__ float g_q[MTOT * Dsz];
__device__ float g_k[MTOT * Dsz];
__device__ float g_v[MTOT * Dsz];
__device__ float g_ctx[MTOT * Dsz];
__device__ float g_lin[MTOT * Dsz];

// ---------------------------------------------------------------------------
// PTX wrappers (plain sm_100-compatible: ldmatrix + mma.sync, no tcgen05)
// ---------------------------------------------------------------------------
__device__ __forceinline__ uint32_t smem_u32(const void* p) {
    uint32_t a;
    asm("{ .reg .u64 t; cvta.to.shared.u64 t, %1; cvt.u32.u64 %0, t; }"
        : "=r"(a) : "l"(p));
    return a;
}

#define LDSM4(r, addr) \
    asm volatile("ldmatrix.sync.aligned.m8n8.x4.shared.b16 {%0,%1,%2,%3}, [%4];" \
        : "=r"((r)[0]), "=r"((r)[1]), "=r"((r)[2]), "=r"((r)[3]) : "r"(addr))
#define LDSM2(r, addr) \
    asm volatile("ldmatrix.sync.aligned.m8n8.x2.shared.b16 {%0,%1}, [%2];" \
        : "=r"((r)[0]), "=r"((r)[1]) : "r"(addr))
#define MMA16816(d, a, b) \
    asm volatile("mma.sync.aligned.m16n8k16.row.col.f32.f16.f16.f32 " \
        "{%0,%1,%2,%3}, {%4,%5,%6,%7}, {%8,%9}, {%0,%1,%2,%3};" \
        : "+f"((d)[0]), "+f"((d)[1]), "+f"((d)[2]), "+f"((d)[3]) \
        : "r"((a)[0]), "r"((a)[1]), "r"((a)[2]), "r"((a)[3]), "r"((b)[0]), "r"((b)[1]))

// ---------------------------------------------------------------------------
// GEMM body: C[8192,512] = A[8192,512] @ W[512,512]^T + bias (+R)
// fp16 2-term split: A -> (hi, lo) fp16; W -> single fp16 (rn).
//   acc = Ahi*W + Alo*W      (fp32 register accumulators)
// Dominant error: W rounding, dot rel-err ~2^-11/sqrt(3) ≈ 2.8e-4 rms.
// CTA tile 128x128, K-chunk 32, 512 threads (16 warps 4x4, warp 32x32).
// Double-buffered fp16 smem ping-pong, register prefetch one chunk ahead.
// Smem rows padded to 80B -> conflict-free ldmatrix (bank start = 20*r % 32).
// ---------------------------------------------------------------------------
#define BM 128
#define BN 128
#define RSTRIDE 80
#define S_AHI 0
#define S_ALO 10240
#define S_BHI 20480
#define STAGE_SZ 30720
#define SMEM_SZ (2 * STAGE_SZ)   // 60 KB dynamic

__device__ __forceinline__ void gemm_body(
    const float* __restrict__ A, const float* __restrict__ W,
    const float* __restrict__ bias, const float* __restrict__ R,
    float* __restrict__ C, char* smbuf)
{
    const uint32_t sbase = smem_u32(smbuf);
    const int tid = threadIdx.x;
    const int lane = tid & 31;
    const int wid = tid >> 5;
    const int wm = wid >> 2;          // 0..3 (M)
    const int wn = wid & 3;           // 0..3 (N)
    const int bm = blockIdx.y * BM;
    const int bn = blockIdx.x * BN;

    const uint4* A4 = (const uint4*)A;   // row stride 128 uint4
    const uint4* W4 = (const uint4*)W;

    // ldmatrix source offsets (relative; add stage base + S_* + kstep*32)
    uint32_t aoff[2], boff[4];
#pragma unroll
    for (int im = 0; im < 2; im++)
        aoff[im] = (uint32_t)((wm * 32 + im * 16 + (lane & 15)) * RSTRIDE +
                              ((lane >> 4) & 1) * 16);
#pragma unroll
    for (int in = 0; in < 4; in++)
        boff[in] = (uint32_t)((wn * 32 + in * 8 + (lane & 7)) * RSTRIDE +
                              ((lane >> 3) & 1) * 16);

    float acc[2][4][4];
#pragma unroll
    for (int im = 0; im < 2; im++)
#pragma unroll
        for (int in = 0; in < 4; in++)
#pragma unroll
            for (int q = 0; q < 4; q++) acc[im][in][q] = 0.f;

    // per-thread load slots: 4 x uint4 per K-chunk (A: 1024 items, B: 1024)
    uint4 pre[4];

    auto prefetch = [&](int kc) {
#pragma unroll
        for (int j = 0; j < 4; j++) {
            int u = tid + j * 512;
            if (u < 1024)
                pre[j] = A4[(size_t)(bm + (u >> 3)) * 128 + kc * 8 + (u & 7)];
            else {
                int v = u - 1024;
                pre[j] = W4[(size_t)(bn + (v >> 3)) * 128 + kc * 8 + (v & 7)];
            }
        }
    };

    auto store_stage = [&](int buf) {
        char* bp = smbuf + buf * STAGE_SZ;
#pragma unroll
        for (int j = 0; j < 4; j++) {
            int u = tid + j * 512;
            float4 f = *reinterpret_cast<float4*>(&pre[j]);
            __half2 h01 = __float22half2_rn(make_float2(f.x, f.y));
            __half2 h23 = __float22half2_rn(make_float2(f.z, f.w));
            uint2 hv = { *reinterpret_cast<uint32_t*>(&h01),
                         *reinterpret_cast<uint32_t*>(&h23) };
            if (u < 1024) {
                // A: hi + lo
                const int off = (u >> 3) * RSTRIDE + (u & 7) * 8;
                float2 fh01 = __half22float2(h01);
                float2 fh23 = __half22float2(h23);
                __half2 l01 = __float22half2_rn(make_float2(f.x - fh01.x, f.y - fh01.y));
                __half2 l23 = __float22half2_rn(make_float2(f.z - fh23.x, f.w - fh23.y));
                uint2 lv = { *reinterpret_cast<uint32_t*>(&l01),
                             *reinterpret_cast<uint32_t*>(&l23) };
                *reinterpret_cast<uint2*>(bp + S_AHI + off) = hv;
                *reinterpret_cast<uint2*>(bp + S_ALO + off) = lv;
            } else {
                // W: hi only
                const int v = u - 1024;
                const int off = (v >> 3) * RSTRIDE + (v & 7) * 8;
                *reinterpret_cast<uint2*>(bp + S_BHI + off) = hv;
            }
        }
    };

    // Pipeline prologue: stage 0 resident, chunk 1 in flight.
    prefetch(0);
    store_stage(0);
    prefetch(1);
    __syncthreads();

    for (int kc = 0; kc < 16; kc++) {
        const uint32_t sb = sbase + (kc & 1) * STAGE_SZ;

#pragma unroll
        for (int ks = 0; ks < 2; ks++) {
            const uint32_t kb = ks * 32;
            uint32_t ah[2][4], bh[4][2], al[2][4];
#pragma unroll
            for (int im = 0; im < 2; im++) LDSM4(ah[im], sb + S_AHI + aoff[im] + kb);
#pragma unroll
            for (int in = 0; in < 4; in++) LDSM2(bh[in], sb + S_BHI + boff[in] + kb);
#pragma unroll
            for (int im = 0; im < 2; im++)
#pragma unroll
                for (int in = 0; in < 4; in++) MMA16816(acc[im][in], ah[im], bh[in]);
#pragma unroll
            for (int im = 0; im < 2; im++) LDSM4(al[im], sb + S_ALO + aoff[im] + kb);
#pragma unroll
            for (int im = 0; im < 2; im++)
#pragma unroll
                for (int in = 0; in < 4; in++) MMA16816(acc[im][in], al[im], bh[in]);
        }

        if (kc < 15) {
            store_stage((kc + 1) & 1);      // consumes pre (chunk kc+1)
            if (kc < 14) prefetch(kc + 2);  // refill pre; lands during next compute
        }
        __syncthreads();
    }

    // Epilogue: fragment d0..d3 -> C[g][2t],C[g][2t+1],C[g+8][2t],C[g+8][2t+1]
    const int g = lane >> 2, tg = lane & 3;
#pragma unroll
    for (int im = 0; im < 2; im++) {
#pragma unroll
        for (int in = 0; in < 4; in++) {
            const int row = bm + wm * 32 + im * 16 + g;
            const int col = bn + wn * 32 + in * 8 + tg * 2;
            const float b0 = bias[col], b1 = bias[col + 1];
            float2 v0 = { acc[im][in][0] + b0, acc[im][in][1] + b1 };
            float2 v1 = { acc[im][in][2] + b0, acc[im][in][3] + b1 };
            const size_t o0 = (size_t)row * Dsz + col;
            const size_t o1 = (size_t)(row + 8) * Dsz + col;
            if (R) {
                v0.x += R[o0];     v0.y += R[o0 + 1];
                v1.x += R[o1];     v1.y += R[o1 + 1];
            }
            *reinterpret_cast<float2*>(&C[o0]) = v0;
            *reinterpret_cast<float2*>(&C[o1]) = v1;
        }
    }
}

// Batched QKV projection: blockIdx.z selects (A, W, bias, C).
__global__ __launch_bounds__(512) void gemm_qkv(
    const float* __restrict__ Q,  const float* __restrict__ Wq, const float* __restrict__ bq, float* __restrict__ Cq,
    const float* __restrict__ K,  const float* __restrict__ Wk, const float* __restrict__ bk, float* __restrict__ Ck,
    const float* __restrict__ V,  const float* __restrict__ Wv, const float* __restrict__ bv, float* __restrict__ Cv)
{
    extern __shared__ char smbuf[];
    const float *A, *W, *bias;
    float* C;
    if (blockIdx.z == 0)      { A = Q; W = Wq; bias = bq; C = Cq; }
    else if (blockIdx.z == 1) { A = K; W = Wk; bias = bk; C = Ck; }
    else                      { A = V; W = Wv; bias = bv; C = Cv; }
    gemm_body(A, W, bias, nullptr, C, smbuf);
}

// Single GEMM (final projection with residual).
__global__ __launch_bounds__(512) void gemm_one(
    const float* __restrict__ A, const float* __restrict__ W,
    const float* __restrict__ bias, const float* __restrict__ R,
    float* __restrict__ C)
{
    extern __shared__ char smbuf[];
    gemm_body(A, W, bias, R, C, smbuf);
}

// ---------------------------------------------------------------------------
// Attention: one warp per (b, h, row). Shuffle-reduced dots, register softmax.
// ---------------------------------------------------------------------------
__global__ __launch_bounds__(256) void attn2(
    const float* __restrict__ gq, const float* __restrict__ gk,
    const float* __restrict__ gv, const unsigned int* __restrict__ mask,
    const float* __restrict__ hyper, float* __restrict__ wout,
    float* __restrict__ ctx)
{
    const int b = blockIdx.x;
    const int h = blockIdx.y;
    const int tid = threadIdx.x;
    const int i = tid >> 5;       // row
    const int lane = tid & 31;    // d

    __shared__ float ks[8][32], vs[8][32];

    const size_t rowbase = ((size_t)b * Ssz + i) * Dsz + (size_t)h * DKsz;
    ks[i][lane] = gk[rowbase + lane];
    vs[i][lane] = gv[rowbase + lane];
    const float qv = gq[rowbase + lane];
    const unsigned int mv = mask[(size_t)b * 64 + i * 8 + (lane & 7)];
    __syncthreads();

    float sc[8];
#pragma unroll
    for (int j = 0; j < 8; j++) {
        float p = qv * ks[j][lane];
        p += __shfl_xor_sync(0xFFFFFFFFu, p, 16);
        p += __shfl_xor_sync(0xFFFFFFFFu, p, 8);
        p += __shfl_xor_sync(0xFFFFFFFFu, p, 4);
        p += __shfl_xor_sync(0xFFFFFFFFu, p, 2);
        p += __shfl_xor_sync(0xFFFFFFFFu, p, 1);
        const unsigned int mj = __shfl_sync(0xFFFFFFFFu, mv, j);
        sc[j] = (mj != 0u) ? -1e9f : p * 0.17677669529663687f;
    }

    float m = sc[0];
#pragma unroll
    for (int j = 1; j < 8; j++) m = fmaxf(m, sc[j]);
    float sum = 0.f;
#pragma unroll
    for (int j = 0; j < 8; j++) { sc[j] = __expf(sc[j] - m); sum += sc[j]; }
    const float inv = 1.f / sum;
#pragma unroll
    for (int j = 0; j < 8; j++) sc[j] *= inv;

    if (lane < 8)
        wout[(((size_t)b * Hsz + h) * Ssz + i) * Ssz + lane] = sc[lane];

    float c = 0.f;
#pragma unroll
    for (int j = 0; j < 8; j++) c += sc[j] * vs[j][lane];
    c *= hyper[(size_t)b * 4096 + h * 256 + i * 32 + lane];
    ctx[rowbase + lane] = c;
}

// ---------------------------------------------------------------------------
// LayerNorm per row (eps=1e-5). 128 threads, float4 each.
// ---------------------------------------------------------------------------
__global__ __launch_bounds__(128) void ln_kernel(
    const float* __restrict__ x, const float* __restrict__ gam,
    const float* __restrict__ bet, float* __restrict__ out)
{
    const int row = blockIdx.x;
    const int tid = threadIdx.x;
    const float4 v = ((const float4*)(x + (size_t)row * Dsz))[tid];

    float s  = v.x + v.y + v.z + v.w;
    float ss = v.x * v.x + v.y * v.y + v.z * v.z + v.w * v.w;
#pragma unroll
    for (int off = 16; off > 0; off >>= 1) {
        s  += __shfl_xor_sync(0xFFFFFFFFu, s,  off);
        ss += __shfl_xor_sync(0xFFFFFFFFu, ss, off);
    }
    __shared__ float sbuf[4], ssbuf[4];
    __shared__ float s_mu, s_rstd;
    if ((tid & 31) == 0) { sbuf[tid >> 5] = s; ssbuf[tid >> 5] = ss; }
    __syncthreads();
    if (tid == 0) {
        const float ts  = sbuf[0] + sbuf[1] + sbuf[2] + sbuf[3];
        const float tss = ssbuf[0] + ssbuf[1] + ssbuf[2] + ssbuf[3];
        const float mu  = ts * (1.f / Dsz);
        const float var = tss * (1.f / Dsz) - mu * mu;
        s_mu = mu;
        s_rstd = rsqrtf(var + 1e-5f);
    }
    __syncthreads();
    const float mu = s_mu, rstd = s_rstd;

    const float4 g4 = ((const float4*)gam)[tid];
    const float4 b4 = ((const float4*)bet)[tid];
    float4 o;
    o.x = (v.x - mu) * rstd * g4.x + b4.x;
    o.y = (v.y - mu) * rstd * g4.y + b4.y;
    o.z = (v.z - mu) * rstd * g4.z + b4.z;
    o.w = (v.w - mu) * rstd * g4.w + b4.w;
    ((float4*)(out + (size_t)row * Dsz))[tid] = o;
}

// ---------------------------------------------------------------------------
extern "C" void kernel_launch(void* const* d_in, const int* in_sizes, int n_in,
                              void* d_out, int out_size)
{
    const float* Q     = (const float*)d_in[0];
    const float* K     = (const float*)d_in[1];
    const float* V     = (const float*)d_in[2];
    const unsigned int* mask = (const unsigned int*)d_in[3];
    const float* hyper = (const float*)d_in[4];
    const float* Wq    = (const float*)d_in[5];
    const float* bq    = (const float*)d_in[6];
    const float* Wk    = (const float*)d_in[7];
    const float* bk    = (const float*)d_in[8];
    const float* Wv    = (const float*)d_in[9];
    const float* bv    = (const float*)d_in[10];
    const float* Wo    = (const float*)d_in[11];
    const float* bo    = (const float*)d_in[12];
    const float* ln_g  = (const float*)d_in[13];
    const float* ln_b  = (const float*)d_in[14];

    float* outp = (float*)d_out;
    float* wout = outp + OUT_ELEMS;

    float *pq, *pk, *pv, *pctx, *plin;
    cudaGetSymbolAddress((void**)&pq,   g_q);
    cudaGetSymbolAddress((void**)&pk,   g_k);
    cudaGetSymbolAddress((void**)&pv,   g_v);
    cudaGetSymbolAddress((void**)&pctx, g_ctx);
    cudaGetSymbolAddress((void**)&plin, g_lin);

    cudaFuncSetAttribute(gemm_qkv, cudaFuncAttributeMaxDynamicSharedMemorySize, SMEM_SZ);
    cudaFuncSetAttribute(gemm_one, cudaFuncAttributeMaxDynamicSharedMemorySize, SMEM_SZ);

    dim3 gq3(Dsz / BN, MTOT / BM, 3);   // (4, 64, 3) = 768 CTAs
    dim3 gg(Dsz / BN, MTOT / BM);       // (4, 64)    = 256 CTAs

    gemm_qkv<<<gq3, 512, SMEM_SZ>>>(Q, Wq, bq, pq,
                                    K, Wk, bk, pk,
                                    V, Wv, bv, pv);

    dim3 agrid(Bsz, Hsz);
    attn2<<<agrid, 256>>>(pq, pk, pv, mask, hyper, wout, pctx);

    gemm_one<<<gg, 512, SMEM_SZ>>>(pctx, Wo, bo, Q, plin);

    ln_kernel<<<MTOT, 128>>>(plin, ln_g, ln_b, outp);
}

// round 9
// speedup vs baseline: 5.0255x; 1.4574x over previous
#include <cuda_runtime.h>
#include <cuda_fp16.h>
#include <cstdint>
#include <math.h>

// Problem constants
#define Bsz   1024
#define Ssz   8
#define Hsz   16
#define DKsz  32
#define Dsz   512
#define MTOT  (Bsz * Ssz)                      // 8192
#define OUT_ELEMS ((size_t)MTOT * Dsz)         // 4194304

// ---------------------------------------------------------------------------
// Scratch (__device__ globals — allocation-free rule)
// ---------------------------------------------------------------------------
__device__ float g_q[MTOT * Dsz];
__device__ float g_k[MTOT * Dsz];
__device__ float g_v[MTOT * Dsz];
__device__ float g_ctx[MTOT * Dsz];
__device__ float g_lin[MTOT * Dsz];

// ---------------------------------------------------------------------------
// PTX wrappers (plain sm_100-compatible: ldmatrix + mma.sync, no tcgen05)
// ---------------------------------------------------------------------------
__device__ __forceinline__ uint32_t smem_u32(const void* p) {
    uint32_t a;
    asm("{ .reg .u64 t; cvta.to.shared.u64 t, %1; cvt.u32.u64 %0, t; }"
        : "=r"(a) : "l"(p));
    return a;
}

#define LDSM4(r, addr) \
    asm volatile("ldmatrix.sync.aligned.m8n8.x4.shared.b16 {%0,%1,%2,%3}, [%4];" \
        : "=r"((r)[0]), "=r"((r)[1]), "=r"((r)[2]), "=r"((r)[3]) : "r"(addr))
#define LDSM2(r, addr) \
    asm volatile("ldmatrix.sync.aligned.m8n8.x2.shared.b16 {%0,%1}, [%2];" \
        : "=r"((r)[0]), "=r"((r)[1]) : "r"(addr))
#define MMA16816(d, a, b) \
    asm volatile("mma.sync.aligned.m16n8k16.row.col.f32.f16.f16.f32 " \
        "{%0,%1,%2,%3}, {%4,%5,%6,%7}, {%8,%9}, {%0,%1,%2,%3};" \
        : "+f"((d)[0]), "+f"((d)[1]), "+f"((d)[2]), "+f"((d)[3]) \
        : "r"((a)[0]), "r"((a)[1]), "r"((a)[2]), "r"((a)[3]), "r"((b)[0]), "r"((b)[1]))

// ---------------------------------------------------------------------------
// GEMM body: C[8192,512] = A[8192,512] @ W[512,512]^T + bias (+R)
// Single-term fp16: A, W both rounded once to fp16 (rn), fp32 accumulate.
// Dot rel-err ~ sqrt(2)*2^-11/sqrt(3) ≈ 4e-4 rms model; measured-calibrated ~3e-4.
// CTA tile 128x128, K-chunk 32, 512 threads (16 warps 4x4, warp 32x32).
// Double-buffered fp16 smem ping-pong, register prefetch one chunk ahead.
// Smem rows padded to 80B -> conflict-free ldmatrix (bank start = 20*r % 32).
// ---------------------------------------------------------------------------
#define BM 128
#define BN 128
#define RSTRIDE 80
#define S_AHI 0
#define S_BHI 10240
#define STAGE_SZ 20480
#define SMEM_SZ (2 * STAGE_SZ)   // 40 KB dynamic

__device__ __forceinline__ void gemm_body(
    const float* __restrict__ A, const float* __restrict__ W,
    const float* __restrict__ bias, const float* __restrict__ R,
    float* __restrict__ C, char* smbuf)
{
    const uint32_t sbase = smem_u32(smbuf);
    const int tid = threadIdx.x;
    const int lane = tid & 31;
    const int wid = tid >> 5;
    const int wm = wid >> 2;          // 0..3 (M)
    const int wn = wid & 3;           // 0..3 (N)
    const int bm = blockIdx.y * BM;
    const int bn = blockIdx.x * BN;

    const uint4* A4 = (const uint4*)A;   // row stride 128 uint4
    const uint4* W4 = (const uint4*)W;

    uint32_t aoff[2], boff[4];
#pragma unroll
    for (int im = 0; im < 2; im++)
        aoff[im] = (uint32_t)((wm * 32 + im * 16 + (lane & 15)) * RSTRIDE +
                              ((lane >> 4) & 1) * 16);
#pragma unroll
    for (int in = 0; in < 4; in++)
        boff[in] = (uint32_t)((wn * 32 + in * 8 + (lane & 7)) * RSTRIDE +
                              ((lane >> 3) & 1) * 16);

    float acc[2][4][4];
#pragma unroll
    for (int im = 0; im < 2; im++)
#pragma unroll
        for (int in = 0; in < 4; in++)
#pragma unroll
            for (int q = 0; q < 4; q++) acc[im][in][q] = 0.f;

    // per-thread load slots: 4 x uint4 per K-chunk (A: 1024 items, B: 1024)
    uint4 pre[4];

    auto prefetch = [&](int kc) {
#pragma unroll
        for (int j = 0; j < 4; j++) {
            int u = tid + j * 512;
            if (u < 1024)
                pre[j] = A4[(size_t)(bm + (u >> 3)) * 128 + kc * 8 + (u & 7)];
            else {
                int v = u - 1024;
                pre[j] = W4[(size_t)(bn + (v >> 3)) * 128 + kc * 8 + (v & 7)];
            }
        }
    };

    auto store_stage = [&](int buf) {
        char* bp = smbuf + buf * STAGE_SZ;
#pragma unroll
        for (int j = 0; j < 4; j++) {
            int u = tid + j * 512;
            float4 f = *reinterpret_cast<float4*>(&pre[j]);
            __half2 h01 = __float22half2_rn(make_float2(f.x, f.y));
            __half2 h23 = __float22half2_rn(make_float2(f.z, f.w));
            uint2 hv = { *reinterpret_cast<uint32_t*>(&h01),
                         *reinterpret_cast<uint32_t*>(&h23) };
            int off, base;
            if (u < 1024) {
                off = (u >> 3) * RSTRIDE + (u & 7) * 8;  base = S_AHI;
            } else {
                int v = u - 1024;
                off = (v >> 3) * RSTRIDE + (v & 7) * 8;  base = S_BHI;
            }
            *reinterpret_cast<uint2*>(bp + base + off) = hv;
        }
    };

    prefetch(0);
    store_stage(0);
    prefetch(1);
    __syncthreads();

    for (int kc = 0; kc < 16; kc++) {
        const uint32_t sb = sbase + (kc & 1) * STAGE_SZ;

#pragma unroll
        for (int ks = 0; ks < 2; ks++) {
            const uint32_t kb = ks * 32;
            uint32_t ah[2][4], bh[4][2];
#pragma unroll
            for (int im = 0; im < 2; im++) LDSM4(ah[im], sb + S_AHI + aoff[im] + kb);
#pragma unroll
            for (int in = 0; in < 4; in++) LDSM2(bh[in], sb + S_BHI + boff[in] + kb);
#pragma unroll
            for (int im = 0; im < 2; im++)
#pragma unroll
                for (int in = 0; in < 4; in++) MMA16816(acc[im][in], ah[im], bh[in]);
        }

        if (kc < 15) {
            store_stage((kc + 1) & 1);
            if (kc < 14) prefetch(kc + 2);
        }
        __syncthreads();
    }

    // Epilogue
    const int g = lane >> 2, tg = lane & 3;
#pragma unroll
    for (int im = 0; im < 2; im++) {
#pragma unroll
        for (int in = 0; in < 4; in++) {
            const int row = bm + wm * 32 + im * 16 + g;
            const int col = bn + wn * 32 + in * 8 + tg * 2;
            const float b0 = bias[col], b1 = bias[col + 1];
            float2 v0 = { acc[im][in][0] + b0, acc[im][in][1] + b1 };
            float2 v1 = { acc[im][in][2] + b0, acc[im][in][3] + b1 };
            const size_t o0 = (size_t)row * Dsz + col;
            const size_t o1 = (size_t)(row + 8) * Dsz + col;
            if (R) {
                v0.x += R[o0];     v0.y += R[o0 + 1];
                v1.x += R[o1];     v1.y += R[o1 + 1];
            }
            *reinterpret_cast<float2*>(&C[o0]) = v0;
            *reinterpret_cast<float2*>(&C[o1]) = v1;
        }
    }
}

__global__ __launch_bounds__(512) void gemm_qkv(
    const float* __restrict__ Q,  const float* __restrict__ Wq, const float* __restrict__ bq, float* __restrict__ Cq,
    const float* __restrict__ K,  const float* __restrict__ Wk, const float* __restrict__ bk, float* __restrict__ Ck,
    const float* __restrict__ V,  const float* __restrict__ Wv, const float* __restrict__ bv, float* __restrict__ Cv)
{
    extern __shared__ char smbuf[];
    const float *A, *W, *bias;
    float* C;
    if (blockIdx.z == 0)      { A = Q; W = Wq; bias = bq; C = Cq; }
    else if (blockIdx.z == 1) { A = K; W = Wk; bias = bk; C = Ck; }
    else                      { A = V; W = Wv; bias = bv; C = Cv; }
    gemm_body(A, W, bias, nullptr, C, smbuf);
}

__global__ __launch_bounds__(512) void gemm_one(
    const float* __restrict__ A, const float* __restrict__ W,
    const float* __restrict__ bias, const float* __restrict__ R,
    float* __restrict__ C)
{
    extern __shared__ char smbuf[];
    gemm_body(A, W, bias, R, C, smbuf);
}

// ---------------------------------------------------------------------------
// Attention v3: one WARP per (b, h) — all 8 rows at once.
// lane = i*4 + dg: i = row (0..7), dg = d-group (0..3, 8 d's each).
// Scores: 4-lane split dots (8 FMA + 2 shfl each); softmax in registers
// (replicated across the 4-lane group, zero communication); AV + hyper gate
// with float4 I/O. No __syncthreads — warps fully independent.
// Smem rows padded to 33 floats -> conflict-free LDS.
// ---------------------------------------------------------------------------
__global__ __launch_bounds__(256) void attn3(
    const float* __restrict__ gq, const float* __restrict__ gk,
    const float* __restrict__ gv, const unsigned int* __restrict__ mask,
    const float* __restrict__ hyper, float* __restrict__ wout,
    float* __restrict__ ctx)
{
    const int b = blockIdx.x;
    const int w = threadIdx.x >> 5;
    const int h = blockIdx.y * 8 + w;
    const int lane = threadIdx.x & 31;
    const int i = lane >> 2;        // row
    const int dg = lane & 3;        // d-group

    __shared__ float qs[8][8][33], ks[8][8][33], vs[8][8][33];

    // Coalesced load: 8 rows x 32 d for q, k, v of this head.
#pragma unroll
    for (int r = 0; r < 8; r++) {
        const size_t base = ((size_t)b * Ssz + r) * Dsz + h * DKsz + lane;
        qs[w][r][lane] = gq[base];
        ks[w][r][lane] = gk[base];
        vs[w][r][lane] = gv[base];
    }
    __syncwarp();

    // Preload this lane's q slice (row i, d = dg*8..dg*8+7).
    float qr[8];
#pragma unroll
    for (int e = 0; e < 8; e++) qr[e] = qs[w][i][dg * 8 + e];

    // Mask row i (8 u32 = 2 x uint4).
    const uint4* m4 = (const uint4*)mask + (size_t)b * 16 + i * 2;
    const uint4 ma = m4[0], mb = m4[1];
    const unsigned int mrow[8] = { ma.x, ma.y, ma.z, ma.w, mb.x, mb.y, mb.z, mb.w };

    float sc[8];
#pragma unroll
    for (int j = 0; j < 8; j++) {
        float p = 0.f;
#pragma unroll
        for (int e = 0; e < 8; e++) p += qr[e] * ks[w][j][dg * 8 + e];
        p += __shfl_xor_sync(0xFFFFFFFFu, p, 1);
        p += __shfl_xor_sync(0xFFFFFFFFu, p, 2);
        sc[j] = (mrow[j] != 0u) ? -1e9f : p * 0.17677669529663687f;
    }

    float m = sc[0];
#pragma unroll
    for (int j = 1; j < 8; j++) m = fmaxf(m, sc[j]);
    float sum = 0.f;
#pragma unroll
    for (int j = 0; j < 8; j++) { sc[j] = __expf(sc[j] - m); sum += sc[j]; }
    const float inv = 1.f / sum;
#pragma unroll
    for (int j = 0; j < 8; j++) sc[j] *= inv;

    // weights out: lane (i,dg) writes j = 2dg, 2dg+1  (64 contiguous floats/warp)
    float2 wv = { sc[dg * 2], sc[dg * 2 + 1] };
    ((float2*)(wout + ((size_t)b * Hsz + h) * 64))[i * 4 + dg] = wv;

    // AV + hyper gate: lane covers d = dg*8 .. dg*8+7 of row i.
    float c[8];
#pragma unroll
    for (int e = 0; e < 8; e++) {
        float cc = 0.f;
#pragma unroll
        for (int j = 0; j < 8; j++) cc += sc[j] * vs[w][j][dg * 8 + e];
        c[e] = cc;
    }
    const size_t hb = (size_t)b * 4096 + h * 256 + i * 32 + dg * 8;
    const float4 hy0 = *(const float4*)(hyper + hb);
    const float4 hy1 = *(const float4*)(hyper + hb + 4);
    const size_t cb = ((size_t)b * Ssz + i) * Dsz + h * DKsz + dg * 8;
    float4 o0 = { c[0] * hy0.x, c[1] * hy0.y, c[2] * hy0.z, c[3] * hy0.w };
    float4 o1 = { c[4] * hy1.x, c[5] * hy1.y, c[6] * hy1.z, c[7] * hy1.w };
    *(float4*)(ctx + cb)     = o0;
    *(float4*)(ctx + cb + 4) = o1;
}

// ---------------------------------------------------------------------------
// LayerNorm v2: one warp per row, no smem, no barriers. 256 thr = 8 rows/blk.
// ---------------------------------------------------------------------------
__global__ __launch_bounds__(256) void ln2(
    const float* __restrict__ x, const float* __restrict__ gam,
    const float* __restrict__ bet, float* __restrict__ out)
{
    const int row = blockIdx.x * 8 + (threadIdx.x >> 5);
    const int lane = threadIdx.x & 31;
    const float4* xr = (const float4*)(x + (size_t)row * Dsz);

    float4 v[4];
    float s = 0.f, ss = 0.f;
#pragma unroll
    for (int t = 0; t < 4; t++) {
        v[t] = xr[lane + t * 32];
        s  += v[t].x + v[t].y + v[t].z + v[t].w;
        ss += v[t].x * v[t].x + v[t].y * v[t].y + v[t].z * v[t].z + v[t].w * v[t].w;
    }
#pragma unroll
    for (int off = 16; off > 0; off >>= 1) {
        s  += __shfl_xor_sync(0xFFFFFFFFu, s,  off);
        ss += __shfl_xor_sync(0xFFFFFFFFu, ss, off);
    }
    const float mu  = s * (1.f / Dsz);
    const float var = ss * (1.f / Dsz) - mu * mu;
    const float rstd = rsqrtf(var + 1e-5f);

    const float4* g4 = (const float4*)gam;
    const float4* b4 = (const float4*)bet;
    float4* o4 = (float4*)(out + (size_t)row * Dsz);
#pragma unroll
    for (int t = 0; t < 4; t++) {
        const float4 g = g4[lane + t * 32];
        const float4 bb = b4[lane + t * 32];
        float4 o;
        o.x = (v[t].x - mu) * rstd * g.x + bb.x;
        o.y = (v[t].y - mu) * rstd * g.y + bb.y;
        o.z = (v[t].z - mu) * rstd * g.z + bb.z;
        o.w = (v[t].w - mu) * rstd * g.w + bb.w;
        o4[lane + t * 32] = o;
    }
}

// ---------------------------------------------------------------------------
extern "C" void kernel_launch(void* const* d_in, const int* in_sizes, int n_in,
                              void* d_out, int out_size)
{
    const float* Q     = (const float*)d_in[0];
    const float* K     = (const float*)d_in[1];
    const float* V     = (const float*)d_in[2];
    const unsigned int* mask = (const unsigned int*)d_in[3];
    const float* hyper = (const float*)d_in[4];
    const float* Wq    = (const float*)d_in[5];
    const float* bq    = (const float*)d_in[6];
    const float* Wk    = (const float*)d_in[7];
    const float* bk    = (const float*)d_in[8];
    const float* Wv    = (const float*)d_in[9];
    const float* bv    = (const float*)d_in[10];
    const float* Wo    = (const float*)d_in[11];
    const float* bo    = (const float*)d_in[12];
    const float* ln_g  = (const float*)d_in[13];
    const float* ln_b  = (const float*)d_in[14];

    float* outp = (float*)d_out;
    float* wout = outp + OUT_ELEMS;

    float *pq, *pk, *pv, *pctx, *plin;
    cudaGetSymbolAddress((void**)&pq,   g_q);
    cudaGetSymbolAddress((void**)&pk,   g_k);
    cudaGetSymbolAddress((void**)&pv,   g_v);
    cudaGetSymbolAddress((void**)&pctx, g_ctx);
    cudaGetSymbolAddress((void**)&plin, g_lin);

    cudaFuncSetAttribute(gemm_qkv, cudaFuncAttributeMaxDynamicSharedMemorySize, SMEM_SZ);
    cudaFuncSetAttribute(gemm_one, cudaFuncAttributeMaxDynamicSharedMemorySize, SMEM_SZ);

    dim3 gq3(Dsz / BN, MTOT / BM, 3);   // (4, 64, 3) = 768 CTAs
    dim3 gg(Dsz / BN, MTOT / BM);       // (4, 64)    = 256 CTAs

    gemm_qkv<<<gq3, 512, SMEM_SZ>>>(Q, Wq, bq, pq,
                                    K, Wk, bk, pk,
                                    V, Wv, bv, pv);

    dim3 agrid(Bsz, Hsz / 8);           // (1024, 2)
    attn3<<<agrid, 256>>>(pq, pk, pv, mask, hyper, wout, pctx);

    gemm_one<<<gg, 512, SMEM_SZ>>>(pctx, Wo, bo, Q, plin);

    ln2<<<MTOT / 8, 256>>>(plin, ln_g, ln_b, outp);
}

// round 10
// speedup vs baseline: 5.3206x; 1.0587x over previous
#include <cuda_runtime.h>
#include <cuda_fp16.h>
#include <cstdint>
#include <math.h>

// Problem constants
#define Bsz   1024
#define Ssz   8
#define Hsz   16
#define DKsz  32
#define Dsz   512
#define MTOT  (Bsz * Ssz)                      // 8192
#define OUT_ELEMS ((size_t)MTOT * Dsz)         // 4194304

// ---------------------------------------------------------------------------
// Scratch (__device__ globals — allocation-free rule)
// ---------------------------------------------------------------------------
__device__ float  g_q[MTOT * Dsz];
__device__ float  g_k[MTOT * Dsz];
__device__ float  g_v[MTOT * Dsz];
__device__ float  g_lin[MTOT * Dsz];
__device__ __half g_qh[MTOT * Dsz];
__device__ __half g_kh[MTOT * Dsz];
__device__ __half g_vh[MTOT * Dsz];
__device__ __half g_ctxh[MTOT * Dsz];
__device__ __half g_wqh[Dsz * Dsz];
__device__ __half g_wkh[Dsz * Dsz];
__device__ __half g_wvh[Dsz * Dsz];
__device__ __half g_woh[Dsz * Dsz];

// ---------------------------------------------------------------------------
// PTX wrappers (plain sm_100-compatible: ldmatrix + mma.sync, no tcgen05)
// ---------------------------------------------------------------------------
__device__ __forceinline__ uint32_t smem_u32(const void* p) {
    uint32_t a;
    asm("{ .reg .u64 t; cvta.to.shared.u64 t, %1; cvt.u32.u64 %0, t; }"
        : "=r"(a) : "l"(p));
    return a;
}

#define LDSM4(r, addr) \
    asm volatile("ldmatrix.sync.aligned.m8n8.x4.shared.b16 {%0,%1,%2,%3}, [%4];" \
        : "=r"((r)[0]), "=r"((r)[1]), "=r"((r)[2]), "=r"((r)[3]) : "r"(addr))
#define LDSM2(r, addr) \
    asm volatile("ldmatrix.sync.aligned.m8n8.x2.shared.b16 {%0,%1}, [%2];" \
        : "=r"((r)[0]), "=r"((r)[1]) : "r"(addr))
#define MMA16816(d, a, b) \
    asm volatile("mma.sync.aligned.m16n8k16.row.col.f32.f16.f16.f32 " \
        "{%0,%1,%2,%3}, {%4,%5,%6,%7}, {%8,%9}, {%0,%1,%2,%3};" \
        : "+f"((d)[0]), "+f"((d)[1]), "+f"((d)[2]), "+f"((d)[3]) \
        : "r"((a)[0]), "r"((a)[1]), "r"((a)[2]), "r"((a)[3]), "r"((b)[0]), "r"((b)[1]))

// ---------------------------------------------------------------------------
// Pre-pass: fp32 -> fp16 (rn) for Q, K, V and the 4 weight matrices.
// 8 floats per thread (2 x float4 in, 1 x uint4 of halves out).
// ---------------------------------------------------------------------------
#define SEG_A (MTOT * Dsz / 8)   // 524288
#define SEG_W (Dsz * Dsz / 8)    // 32768
#define CONV_TOTAL (3 * SEG_A + 4 * SEG_W)

__global__ __launch_bounds__(256) void conv_fp16(
    const float* __restrict__ Q, const float* __restrict__ K, const float* __restrict__ V,
    const float* __restrict__ Wq, const float* __restrict__ Wk,
    const float* __restrict__ Wv, const float* __restrict__ Wo,
    __half* __restrict__ Qh, __half* __restrict__ Kh, __half* __restrict__ Vh,
    __half* __restrict__ Wqh, __half* __restrict__ Wkh,
    __half* __restrict__ Wvh, __half* __restrict__ Woh)
{
    int idx = blockIdx.x * 256 + threadIdx.x;
    if (idx >= CONV_TOTAL) return;
    const float* src;  __half* dst;
    if (idx < SEG_A)          { src = Q; dst = Qh; }
    else if (idx < 2 * SEG_A) { src = K; dst = Kh; idx -= SEG_A; }
    else if (idx < 3 * SEG_A) { src = V; dst = Vh; idx -= 2 * SEG_A; }
    else {
        idx -= 3 * SEG_A;
        if (idx < SEG_W)          { src = Wq; dst = Wqh; }
        else if (idx < 2 * SEG_W) { src = Wk; dst = Wkh; idx -= SEG_W; }
        else if (idx < 3 * SEG_W) { src = Wv; dst = Wvh; idx -= 2 * SEG_W; }
        else                      { src = Wo; dst = Woh; idx -= 3 * SEG_W; }
    }
    const float4 f0 = ((const float4*)src)[idx * 2];
    const float4 f1 = ((const float4*)src)[idx * 2 + 1];
    __half2 h0 = __float22half2_rn(make_float2(f0.x, f0.y));
    __half2 h1 = __float22half2_rn(make_float2(f0.z, f0.w));
    __half2 h2 = __float22half2_rn(make_float2(f1.x, f1.y));
    __half2 h3 = __float22half2_rn(make_float2(f1.z, f1.w));
    uint4 o = { *reinterpret_cast<uint32_t*>(&h0), *reinterpret_cast<uint32_t*>(&h1),
                *reinterpret_cast<uint32_t*>(&h2), *reinterpret_cast<uint32_t*>(&h3) };
    ((uint4*)dst)[idx] = o;
}

// ---------------------------------------------------------------------------
// GEMM body: C[8192,512] = A[8192,512] @ W[512,512]^T + bias (+R)
// A, W pre-converted fp16; fp32 accumulate, fp32 out.
// CTA tile 128x128, K-chunk 32, 512 threads (16 warps 4x4, warp 32x32).
// Double-buffered smem ping-pong; per chunk: 2 LDG.128 + 2 STS.128 / thread.
// Smem rows: 64 B data, 80 B stride -> conflict-free ldmatrix.
// ---------------------------------------------------------------------------
#define BM 128
#define BN 128
#define RSTRIDE 80
#define S_AHI 0
#define S_BHI 10240
#define STAGE_SZ 20480
#define SMEM_SZ (2 * STAGE_SZ)   // 40 KB dynamic

__device__ __forceinline__ void gemm_body(
    const __half* __restrict__ A, const __half* __restrict__ W,
    const float* __restrict__ bias, const float* __restrict__ R,
    float* __restrict__ C, char* smbuf)
{
    const uint32_t sbase = smem_u32(smbuf);
    const int tid = threadIdx.x;
    const int lane = tid & 31;
    const int wid = tid >> 5;
    const int wm = wid >> 2;          // 0..3 (M)
    const int wn = wid & 3;           // 0..3 (N)
    const int bm = blockIdx.y * BM;
    const int bn = blockIdx.x * BN;

    const uint4* A4 = (const uint4*)A;   // fp16 row = 64 uint4
    const uint4* W4 = (const uint4*)W;

    uint32_t aoff[2], boff[4];
#pragma unroll
    for (int im = 0; im < 2; im++)
        aoff[im] = (uint32_t)((wm * 32 + im * 16 + (lane & 15)) * RSTRIDE +
                              ((lane >> 4) & 1) * 16);
#pragma unroll
    for (int in = 0; in < 4; in++)
        boff[in] = (uint32_t)((wn * 32 + in * 8 + (lane & 7)) * RSTRIDE +
                              ((lane >> 3) & 1) * 16);

    float acc[2][4][4];
#pragma unroll
    for (int im = 0; im < 2; im++)
#pragma unroll
        for (int in = 0; in < 4; in++)
#pragma unroll
            for (int q = 0; q < 4; q++) acc[im][in][q] = 0.f;

    // per-thread: 2 x uint4 per K-chunk (A: 512 items, B: 512 items)
    uint4 pre[2];
    const int r  = tid >> 2;          // row within tile (0..127)
    const int qd = tid & 3;           // 16B quarter within 64B chunk-row
    const int soff = r * RSTRIDE + qd * 16;

    auto prefetch = [&](int kc) {
        pre[0] = A4[(size_t)(bm + r) * 64 + kc * 4 + qd];
        pre[1] = W4[(size_t)(bn + r) * 64 + kc * 4 + qd];
    };
    auto store_stage = [&](int buf) {
        char* bp = smbuf + buf * STAGE_SZ;
        *reinterpret_cast<uint4*>(bp + S_AHI + soff) = pre[0];
        *reinterpret_cast<uint4*>(bp + S_BHI + soff) = pre[1];
    };

    prefetch(0);
    store_stage(0);
    prefetch(1);
    __syncthreads();

    for (int kc = 0; kc < 16; kc++) {
        const uint32_t sb = sbase + (kc & 1) * STAGE_SZ;

#pragma unroll
        for (int ks = 0; ks < 2; ks++) {
            const uint32_t kb = ks * 32;
            uint32_t ah[2][4], bh[4][2];
#pragma unroll
            for (int im = 0; im < 2; im++) LDSM4(ah[im], sb + S_AHI + aoff[im] + kb);
#pragma unroll
            for (int in = 0; in < 4; in++) LDSM2(bh[in], sb + S_BHI + boff[in] + kb);
#pragma unroll
            for (int im = 0; im < 2; im++)
#pragma unroll
                for (int in = 0; in < 4; in++) MMA16816(acc[im][in], ah[im], bh[in]);
        }

        if (kc < 15) {
            store_stage((kc + 1) & 1);
            if (kc < 14) prefetch(kc + 2);
        }
        __syncthreads();
    }

    // Epilogue
    const int g = lane >> 2, tg = lane & 3;
#pragma unroll
    for (int im = 0; im < 2; im++) {
#pragma unroll
        for (int in = 0; in < 4; in++) {
            const int row = bm + wm * 32 + im * 16 + g;
            const int col = bn + wn * 32 + in * 8 + tg * 2;
            const float b0 = bias[col], b1 = bias[col + 1];
            float2 v0 = { acc[im][in][0] + b0, acc[im][in][1] + b1 };
            float2 v1 = { acc[im][in][2] + b0, acc[im][in][3] + b1 };
            const size_t o0 = (size_t)row * Dsz + col;
            const size_t o1 = (size_t)(row + 8) * Dsz + col;
            if (R) {
                v0.x += R[o0];     v0.y += R[o0 + 1];
                v1.x += R[o1];     v1.y += R[o1 + 1];
            }
            *reinterpret_cast<float2*>(&C[o0]) = v0;
            *reinterpret_cast<float2*>(&C[o1]) = v1;
        }
    }
}

__global__ __launch_bounds__(512) void gemm_qkv(
    const __half* __restrict__ Qh, const __half* __restrict__ Wqh, const float* __restrict__ bq, float* __restrict__ Cq,
    const __half* __restrict__ Kh, const __half* __restrict__ Wkh, const float* __restrict__ bk, float* __restrict__ Ck,
    const __half* __restrict__ Vh, const __half* __restrict__ Wvh, const float* __restrict__ bv, float* __restrict__ Cv)
{
    extern __shared__ char smbuf[];
    const __half *A, *W;
    const float* bias;
    float* C;
    if (blockIdx.z == 0)      { A = Qh; W = Wqh; bias = bq; C = Cq; }
    else if (blockIdx.z == 1) { A = Kh; W = Wkh; bias = bk; C = Ck; }
    else                      { A = Vh; W = Wvh; bias = bv; C = Cv; }
    gemm_body(A, W, bias, nullptr, C, smbuf);
}

__global__ __launch_bounds__(512) void gemm_one(
    const __half* __restrict__ A, const __half* __restrict__ W,
    const float* __restrict__ bias, const float* __restrict__ R,
    float* __restrict__ C)
{
    extern __shared__ char smbuf[];
    gemm_body(A, W, bias, R, C, smbuf);
}

// ---------------------------------------------------------------------------
// Attention v3: one WARP per (b, h); emits ctx directly as fp16 (rounded once
// — same rounding point the GEMM used before, so math is unchanged).
// ---------------------------------------------------------------------------
__global__ __launch_bounds__(256) void attn3(
    const float* __restrict__ gq, const float* __restrict__ gk,
    const float* __restrict__ gv, const unsigned int* __restrict__ mask,
    const float* __restrict__ hyper, float* __restrict__ wout,
    __half* __restrict__ ctxh)
{
    const int b = blockIdx.x;
    const int w = threadIdx.x >> 5;
    const int h = blockIdx.y * 8 + w;
    const int lane = threadIdx.x & 31;
    const int i = lane >> 2;        // row
    const int dg = lane & 3;        // d-group

    __shared__ float qs[8][8][33], ks[8][8][33], vs[8][8][33];

#pragma unroll
    for (int r = 0; r < 8; r++) {
        const size_t base = ((size_t)b * Ssz + r) * Dsz + h * DKsz + lane;
        qs[w][r][lane] = gq[base];
        ks[w][r][lane] = gk[base];
        vs[w][r][lane] = gv[base];
    }
    __syncwarp();

    float qr[8];
#pragma unroll
    for (int e = 0; e < 8; e++) qr[e] = qs[w][i][dg * 8 + e];

    const uint4* m4 = (const uint4*)mask + (size_t)b * 16 + i * 2;
    const uint4 ma = m4[0], mb = m4[1];
    const unsigned int mrow[8] = { ma.x, ma.y, ma.z, ma.w, mb.x, mb.y, mb.z, mb.w };

    float sc[8];
#pragma unroll
    for (int j = 0; j < 8; j++) {
        float p = 0.f;
#pragma unroll
        for (int e = 0; e < 8; e++) p += qr[e] * ks[w][j][dg * 8 + e];
        p += __shfl_xor_sync(0xFFFFFFFFu, p, 1);
        p += __shfl_xor_sync(0xFFFFFFFFu, p, 2);
        sc[j] = (mrow[j] != 0u) ? -1e9f : p * 0.17677669529663687f;
    }

    float m = sc[0];
#pragma unroll
    for (int j = 1; j < 8; j++) m = fmaxf(m, sc[j]);
    float sum = 0.f;
#pragma unroll
    for (int j = 0; j < 8; j++) { sc[j] = __expf(sc[j] - m); sum += sc[j]; }
    const float inv = 1.f / sum;
#pragma unroll
    for (int j = 0; j < 8; j++) sc[j] *= inv;

    float2 wv = { sc[dg * 2], sc[dg * 2 + 1] };
    ((float2*)(wout + ((size_t)b * Hsz + h) * 64))[i * 4 + dg] = wv;

    float c[8];
#pragma unroll
    for (int e = 0; e < 8; e++) {
        float cc = 0.f;
#pragma unroll
        for (int j = 0; j < 8; j++) cc += sc[j] * vs[w][j][dg * 8 + e];
        c[e] = cc;
    }
    const size_t hb = (size_t)b * 4096 + h * 256 + i * 32 + dg * 8;
    const float4 hy0 = *(const float4*)(hyper + hb);
    const float4 hy1 = *(const float4*)(hyper + hb + 4);
    __half2 p0 = __float22half2_rn(make_float2(c[0] * hy0.x, c[1] * hy0.y));
    __half2 p1 = __float22half2_rn(make_float2(c[2] * hy0.z, c[3] * hy0.w));
    __half2 p2 = __float22half2_rn(make_float2(c[4] * hy1.x, c[5] * hy1.y));
    __half2 p3 = __float22half2_rn(make_float2(c[6] * hy1.z, c[7] * hy1.w));
    uint4 ov = { *reinterpret_cast<uint32_t*>(&p0), *reinterpret_cast<uint32_t*>(&p1),
                 *reinterpret_cast<uint32_t*>(&p2), *reinterpret_cast<uint32_t*>(&p3) };
    const size_t cb = ((size_t)b * Ssz + i) * Dsz + h * DKsz + dg * 8;
    *reinterpret_cast<uint4*>(ctxh + cb) = ov;
}

// ---------------------------------------------------------------------------
// LayerNorm: one warp per row, no smem, no barriers. 256 thr = 8 rows/blk.
// ---------------------------------------------------------------------------
__global__ __launch_bounds__(256) void ln2(
    const float* __restrict__ x, const float* __restrict__ gam,
    const float* __restrict__ bet, float* __restrict__ out)
{
    const int row = blockIdx.x * 8 + (threadIdx.x >> 5);
    const int lane = threadIdx.x & 31;
    const float4* xr = (const float4*)(x + (size_t)row * Dsz);

    float4 v[4];
    float s = 0.f, ss = 0.f;
#pragma unroll
    for (int t = 0; t < 4; t++) {
        v[t] = xr[lane + t * 32];
        s  += v[t].x + v[t].y + v[t].z + v[t].w;
        ss += v[t].x * v[t].x + v[t].y * v[t].y + v[t].z * v[t].z + v[t].w * v[t].w;
    }
#pragma unroll
    for (int off = 16; off > 0; off >>= 1) {
        s  += __shfl_xor_sync(0xFFFFFFFFu, s,  off);
        ss += __shfl_xor_sync(0xFFFFFFFFu, ss, off);
    }
    const float mu  = s * (1.f / Dsz);
    const float var = ss * (1.f / Dsz) - mu * mu;
    const float rstd = rsqrtf(var + 1e-5f);

    const float4* g4 = (const float4*)gam;
    const float4* b4 = (const float4*)bet;
    float4* o4 = (float4*)(out + (size_t)row * Dsz);
#pragma unroll
    for (int t = 0; t < 4; t++) {
        const float4 g = g4[lane + t * 32];
        const float4 bb = b4[lane + t * 32];
        float4 o;
        o.x = (v[t].x - mu) * rstd * g.x + bb.x;
        o.y = (v[t].y - mu) * rstd * g.y + bb.y;
        o.z = (v[t].z - mu) * rstd * g.z + bb.z;
        o.w = (v[t].w - mu) * rstd * g.w + bb.w;
        o4[lane + t * 32] = o;
    }
}

// ---------------------------------------------------------------------------
extern "C" void kernel_launch(void* const* d_in, const int* in_sizes, int n_in,
                              void* d_out, int out_size)
{
    const float* Q     = (const float*)d_in[0];
    const float* K     = (const float*)d_in[1];
    const float* V     = (const float*)d_in[2];
    const unsigned int* mask = (const unsigned int*)d_in[3];
    const float* hyper = (const float*)d_in[4];
    const float* Wq    = (const float*)d_in[5];
    const float* bq    = (const float*)d_in[6];
    const float* Wk    = (const float*)d_in[7];
    const float* bk    = (const float*)d_in[8];
    const float* Wv    = (const float*)d_in[9];
    const float* bv    = (const float*)d_in[10];
    const float* Wo    = (const float*)d_in[11];
    const float* bo    = (const float*)d_in[12];
    const float* ln_g  = (const float*)d_in[13];
    const float* ln_b  = (const float*)d_in[14];

    float* outp = (float*)d_out;
    float* wout = outp + OUT_ELEMS;

    float *pq, *pk, *pv, *plin;
    __half *pqh, *pkh, *pvh, *pctxh, *pwqh, *pwkh, *pwvh, *pwoh;
    cudaGetSymbolAddress((void**)&pq,    g_q);
    cudaGetSymbolAddress((void**)&pk,    g_k);
    cudaGetSymbolAddress((void**)&pv,    g_v);
    cudaGetSymbolAddress((void**)&plin,  g_lin);
    cudaGetSymbolAddress((void**)&pqh,   g_qh);
    cudaGetSymbolAddress((void**)&pkh,   g_kh);
    cudaGetSymbolAddress((void**)&pvh,   g_vh);
    cudaGetSymbolAddress((void**)&pctxh, g_ctxh);
    cudaGetSymbolAddress((void**)&pwqh,  g_wqh);
    cudaGetSymbolAddress((void**)&pwkh,  g_wkh);
    cudaGetSymbolAddress((void**)&pwvh,  g_wvh);
    cudaGetSymbolAddress((void**)&pwoh,  g_woh);

    cudaFuncSetAttribute(gemm_qkv, cudaFuncAttributeMaxDynamicSharedMemorySize, SMEM_SZ);
    cudaFuncSetAttribute(gemm_one, cudaFuncAttributeMaxDynamicSharedMemorySize, SMEM_SZ);

    conv_fp16<<<(CONV_TOTAL + 255) / 256, 256>>>(Q, K, V, Wq, Wk, Wv, Wo,
                                                 pqh, pkh, pvh, pwqh, pwkh, pwvh, pwoh);

    dim3 gq3(Dsz / BN, MTOT / BM, 3);   // (4, 64, 3) = 768 CTAs
    gemm_qkv<<<gq3, 512, SMEM_SZ>>>(pqh, pwqh, bq, pq,
                                    pkh, pwkh, bk, pk,
                                    pvh, pwvh, bv, pv);

    dim3 agrid(Bsz, Hsz / 8);           // (1024, 2)
    attn3<<<agrid, 256>>>(pq, pk, pv, mask, hyper, wout, pctxh);

    dim3 gg(Dsz / BN, MTOT / BM);       // (4, 64)
    gemm_one<<<gg, 512, SMEM_SZ>>>(pctxh, pwoh, bo, Q, plin);

    ln2<<<MTOT / 8, 256>>>(plin, ln_g, ln_b, outp);
}

// round 11
// speedup vs baseline: 6.3112x; 1.1862x over previous
#include <cuda_runtime.h>
#include <cuda_fp16.h>
#include <cstdint>
#include <math.h>

// Problem constants
#define Bsz   1024
#define Ssz   8
#define Hsz   16
#define DKsz  32
#define Dsz   512
#define MTOT  (Bsz * Ssz)                      // 8192
#define OUT_ELEMS ((size_t)MTOT * Dsz)         // 4194304

// ---------------------------------------------------------------------------
// Scratch (__device__ globals — allocation-free rule)
// ---------------------------------------------------------------------------
__device__ float  g_q[MTOT * Dsz];
__device__ float  g_k[MTOT * Dsz];
__device__ float  g_v[MTOT * Dsz];
__device__ float  g_lin[MTOT * Dsz];
__device__ __half g_qh[MTOT * Dsz];
__device__ __half g_kh[MTOT * Dsz];
__device__ __half g_vh[MTOT * Dsz];
__device__ __half g_ctxh[MTOT * Dsz];
__device__ __half g_wqh[Dsz * Dsz];
__device__ __half g_wkh[Dsz * Dsz];
__device__ __half g_wvh[Dsz * Dsz];
__device__ __half g_woh[Dsz * Dsz];

// ---------------------------------------------------------------------------
// PTX wrappers (plain sm_100-compatible: ldmatrix + mma.sync + cp.async)
// ---------------------------------------------------------------------------
__device__ __forceinline__ uint32_t smem_u32(const void* p) {
    uint32_t a;
    asm("{ .reg .u64 t; cvta.to.shared.u64 t, %1; cvt.u32.u64 %0, t; }"
        : "=r"(a) : "l"(p));
    return a;
}

#define LDSM4(r, addr) \
    asm volatile("ldmatrix.sync.aligned.m8n8.x4.shared.b16 {%0,%1,%2,%3}, [%4];" \
        : "=r"((r)[0]), "=r"((r)[1]), "=r"((r)[2]), "=r"((r)[3]) : "r"(addr))
#define LDSM2(r, addr) \
    asm volatile("ldmatrix.sync.aligned.m8n8.x2.shared.b16 {%0,%1}, [%2];" \
        : "=r"((r)[0]), "=r"((r)[1]) : "r"(addr))
#define MMA16816(d, a, b) \
    asm volatile("mma.sync.aligned.m16n8k16.row.col.f32.f16.f16.f32 " \
        "{%0,%1,%2,%3}, {%4,%5,%6,%7}, {%8,%9}, {%0,%1,%2,%3};" \
        : "+f"((d)[0]), "+f"((d)[1]), "+f"((d)[2]), "+f"((d)[3]) \
        : "r"((a)[0]), "r"((a)[1]), "r"((a)[2]), "r"((a)[3]), "r"((b)[0]), "r"((b)[1]))
#define CP_ASYNC16(dst, src) \
    asm volatile("cp.async.cg.shared.global [%0], [%1], 16;" :: "r"(dst), "l"(src))
#define CP_COMMIT() asm volatile("cp.async.commit_group;")
#define CP_WAIT1()  asm volatile("cp.async.wait_group 1;")
#define CP_WAIT0()  asm volatile("cp.async.wait_group 0;")

// ---------------------------------------------------------------------------
// Pre-pass: fp32 -> fp16 (rn) for Q, K, V and the 4 weight matrices.
// ---------------------------------------------------------------------------
#define SEG_A (MTOT * Dsz / 8)   // 524288
#define SEG_W (Dsz * Dsz / 8)    // 32768
#define CONV_TOTAL (3 * SEG_A + 4 * SEG_W)

__global__ __launch_bounds__(256) void conv_fp16(
    const float* __restrict__ Q, const float* __restrict__ K, const float* __restrict__ V,
    const float* __restrict__ Wq, const float* __restrict__ Wk,
    const float* __restrict__ Wv, const float* __restrict__ Wo,
    __half* __restrict__ Qh, __half* __restrict__ Kh, __half* __restrict__ Vh,
    __half* __restrict__ Wqh, __half* __restrict__ Wkh,
    __half* __restrict__ Wvh, __half* __restrict__ Woh)
{
    int idx = blockIdx.x * 256 + threadIdx.x;
    if (idx >= CONV_TOTAL) return;
    const float* src;  __half* dst;
    if (idx < SEG_A)          { src = Q; dst = Qh; }
    else if (idx < 2 * SEG_A) { src = K; dst = Kh; idx -= SEG_A; }
    else if (idx < 3 * SEG_A) { src = V; dst = Vh; idx -= 2 * SEG_A; }
    else {
        idx -= 3 * SEG_A;
        if (idx < SEG_W)          { src = Wq; dst = Wqh; }
        else if (idx < 2 * SEG_W) { src = Wk; dst = Wkh; idx -= SEG_W; }
        else if (idx < 3 * SEG_W) { src = Wv; dst = Wvh; idx -= 2 * SEG_W; }
        else                      { src = Wo; dst = Woh; idx -= 3 * SEG_W; }
    }
    const float4 f0 = ((const float4*)src)[idx * 2];
    const float4 f1 = ((const float4*)src)[idx * 2 + 1];
    __half2 h0 = __float22half2_rn(make_float2(f0.x, f0.y));
    __half2 h1 = __float22half2_rn(make_float2(f0.z, f0.w));
    __half2 h2 = __float22half2_rn(make_float2(f1.x, f1.y));
    __half2 h3 = __float22half2_rn(make_float2(f1.z, f1.w));
    uint4 o = { *reinterpret_cast<uint32_t*>(&h0), *reinterpret_cast<uint32_t*>(&h1),
                *reinterpret_cast<uint32_t*>(&h2), *reinterpret_cast<uint32_t*>(&h3) };
    ((uint4*)dst)[idx] = o;
}

// ---------------------------------------------------------------------------
// GEMM body: C[8192,512] = A[8192,512] @ W[512,512]^T + bias (+R)
// fp16 inputs, fp32 accumulate. CTA tile 128x128, K-chunk 32, 512 threads.
// 3-stage cp.async pipeline, ONE __syncthreads per chunk.
// __launch_bounds__(512, 2) -> <=64 regs -> 2 CTAs/SM (32 warps) for latency.
// Smem rows: 64 B data, 80 B stride -> conflict-free ldmatrix.
// ---------------------------------------------------------------------------
#define BM 128
#define BN 128
#define RSTRIDE 80
#define S_AHI 0
#define S_BHI 10240
#define STAGE_SZ 20480
#define SMEM_SZ (3 * STAGE_SZ)   // 60 KB dynamic

__device__ __forceinline__ void gemm_body(
    const __half* __restrict__ A, const __half* __restrict__ W,
    const float* __restrict__ bias, const float* __restrict__ R,
    float* __restrict__ C, char* smbuf)
{
    const uint32_t sbase = smem_u32(smbuf);
    const int tid = threadIdx.x;
    const int lane = tid & 31;
    const int wid = tid >> 5;
    const int wm = wid >> 2;          // 0..3 (M)
    const int wn = wid & 3;           // 0..3 (N)
    const int bm = blockIdx.y * BM;
    const int bn = blockIdx.x * BN;

    // Loader mapping: r = row in tile (0..127), qd = 16B quarter of 64B row.
    const int r  = tid >> 2;
    const int qd = tid & 3;
    const uint32_t soff = (uint32_t)(r * RSTRIDE + qd * 16);
    const __half* asrc = A + (size_t)(bm + r) * Dsz + qd * 8;
    const __half* wsrc = W + (size_t)(bn + r) * Dsz + qd * 8;

    auto issue = [&](int kc) {
        const uint32_t st = sbase + (kc % 3) * STAGE_SZ;
        CP_ASYNC16(st + S_AHI + soff, asrc + kc * 32);
        CP_ASYNC16(st + S_BHI + soff, wsrc + kc * 32);
        CP_COMMIT();
    };

    uint32_t aoff[2], boff[4];
#pragma unroll
    for (int im = 0; im < 2; im++)
        aoff[im] = (uint32_t)((wm * 32 + im * 16 + (lane & 15)) * RSTRIDE +
                              ((lane >> 4) & 1) * 16);
#pragma unroll
    for (int in = 0; in < 4; in++)
        boff[in] = (uint32_t)((wn * 32 + in * 8 + (lane & 7)) * RSTRIDE +
                              ((lane >> 3) & 1) * 16);

    float acc[2][4][4];
#pragma unroll
    for (int im = 0; im < 2; im++)
#pragma unroll
        for (int in = 0; in < 4; in++)
#pragma unroll
            for (int q = 0; q < 4; q++) acc[im][in][q] = 0.f;

    issue(0);
    issue(1);
    CP_WAIT1();            // chunk 0 landed
    __syncthreads();

    for (int kc = 0; kc < 16; kc++) {
        const uint32_t sb = sbase + (kc % 3) * STAGE_SZ;

#pragma unroll
        for (int ks = 0; ks < 2; ks++) {
            const uint32_t kb = ks * 32;
            uint32_t ah[2][4], bh[4][2];
#pragma unroll
            for (int im = 0; im < 2; im++) LDSM4(ah[im], sb + S_AHI + aoff[im] + kb);
#pragma unroll
            for (int in = 0; in < 4; in++) LDSM2(bh[in], sb + S_BHI + boff[in] + kb);
#pragma unroll
            for (int im = 0; im < 2; im++)
#pragma unroll
                for (int in = 0; in < 4; in++) MMA16816(acc[im][in], ah[im], bh[in]);
        }

        // Buffer (kc+2)%3 was consumed at iteration kc-1; the barrier below
        // (previous iteration) guarantees all warps are done with it.
        if (kc < 14) {
            issue(kc + 2);
            CP_WAIT1();    // chunk kc+1 landed
        } else {
            CP_WAIT0();    // drain tail (chunk 15)
        }
        __syncthreads();
    }

    // Epilogue
    const int g = lane >> 2, tg = lane & 3;
#pragma unroll
    for (int im = 0; im < 2; im++) {
#pragma unroll
        for (int in = 0; in < 4; in++) {
            const int row = bm + wm * 32 + im * 16 + g;
            const int col = bn + wn * 32 + in * 8 + tg * 2;
            const float b0 = bias[col], b1 = bias[col + 1];
            float2 v0 = { acc[im][in][0] + b0, acc[im][in][1] + b1 };
            float2 v1 = { acc[im][in][2] + b0, acc[im][in][3] + b1 };
            const size_t o0 = (size_t)row * Dsz + col;
            const size_t o1 = (size_t)(row + 8) * Dsz + col;
            if (R) {
                v0.x += R[o0];     v0.y += R[o0 + 1];
                v1.x += R[o1];     v1.y += R[o1 + 1];
            }
            *reinterpret_cast<float2*>(&C[o0]) = v0;
            *reinterpret_cast<float2*>(&C[o1]) = v1;
        }
    }
}

__global__ __launch_bounds__(512, 2) void gemm_qkv(
    const __half* __restrict__ Qh, const __half* __restrict__ Wqh, const float* __restrict__ bq, float* __restrict__ Cq,
    const __half* __restrict__ Kh, const __half* __restrict__ Wkh, const float* __restrict__ bk, float* __restrict__ Ck,
    const __half* __restrict__ Vh, const __half* __restrict__ Wvh, const float* __restrict__ bv, float* __restrict__ Cv)
{
    extern __shared__ char smbuf[];
    const __half *A, *W;
    const float* bias;
    float* C;
    if (blockIdx.z == 0)      { A = Qh; W = Wqh; bias = bq; C = Cq; }
    else if (blockIdx.z == 1) { A = Kh; W = Wkh; bias = bk; C = Ck; }
    else                      { A = Vh; W = Wvh; bias = bv; C = Cv; }
    gemm_body(A, W, bias, nullptr, C, smbuf);
}

__global__ __launch_bounds__(512, 2) void gemm_one(
    const __half* __restrict__ A, const __half* __restrict__ W,
    const float* __restrict__ bias, const float* __restrict__ R,
    float* __restrict__ C)
{
    extern __shared__ char smbuf[];
    gemm_body(A, W, bias, R, C, smbuf);
}

// ---------------------------------------------------------------------------
// Attention v3: one WARP per (b, h); ctx emitted directly as fp16.
// ---------------------------------------------------------------------------
__global__ __launch_bounds__(256) void attn3(
    const float* __restrict__ gq, const float* __restrict__ gk,
    const float* __restrict__ gv, const unsigned int* __restrict__ mask,
    const float* __restrict__ hyper, float* __restrict__ wout,
    __half* __restrict__ ctxh)
{
    const int b = blockIdx.x;
    const int w = threadIdx.x >> 5;
    const int h = blockIdx.y * 8 + w;
    const int lane = threadIdx.x & 31;
    const int i = lane >> 2;        // row
    const int dg = lane & 3;        // d-group

    __shared__ float qs[8][8][33], ks[8][8][33], vs[8][8][33];

#pragma unroll
    for (int r = 0; r < 8; r++) {
        const size_t base = ((size_t)b * Ssz + r) * Dsz + h * DKsz + lane;
        qs[w][r][lane] = gq[base];
        ks[w][r][lane] = gk[base];
        vs[w][r][lane] = gv[base];
    }
    __syncwarp();

    float qr[8];
#pragma unroll
    for (int e = 0; e < 8; e++) qr[e] = qs[w][i][dg * 8 + e];

    const uint4* m4 = (const uint4*)mask + (size_t)b * 16 + i * 2;
    const uint4 ma = m4[0], mb = m4[1];
    const unsigned int mrow[8] = { ma.x, ma.y, ma.z, ma.w, mb.x, mb.y, mb.z, mb.w };

    float sc[8];
#pragma unroll
    for (int j = 0; j < 8; j++) {
        float p = 0.f;
#pragma unroll
        for (int e = 0; e < 8; e++) p += qr[e] * ks[w][j][dg * 8 + e];
        p += __shfl_xor_sync(0xFFFFFFFFu, p, 1);
        p += __shfl_xor_sync(0xFFFFFFFFu, p, 2);
        sc[j] = (mrow[j] != 0u) ? -1e9f : p * 0.17677669529663687f;
    }

    float m = sc[0];
#pragma unroll
    for (int j = 1; j < 8; j++) m = fmaxf(m, sc[j]);
    float sum = 0.f;
#pragma unroll
    for (int j = 0; j < 8; j++) { sc[j] = __expf(sc[j] - m); sum += sc[j]; }
    const float inv = 1.f / sum;
#pragma unroll
    for (int j = 0; j < 8; j++) sc[j] *= inv;

    float2 wv = { sc[dg * 2], sc[dg * 2 + 1] };
    ((float2*)(wout + ((size_t)b * Hsz + h) * 64))[i * 4 + dg] = wv;

    float c[8];
#pragma unroll
    for (int e = 0; e < 8; e++) {
        float cc = 0.f;
#pragma unroll
        for (int j = 0; j < 8; j++) cc += sc[j] * vs[w][j][dg * 8 + e];
        c[e] = cc;
    }
    const size_t hb = (size_t)b * 4096 + h * 256 + i * 32 + dg * 8;
    const float4 hy0 = *(const float4*)(hyper + hb);
    const float4 hy1 = *(const float4*)(hyper + hb + 4);
    __half2 p0 = __float22half2_rn(make_float2(c[0] * hy0.x, c[1] * hy0.y));
    __half2 p1 = __float22half2_rn(make_float2(c[2] * hy0.z, c[3] * hy0.w));
    __half2 p2 = __float22half2_rn(make_float2(c[4] * hy1.x, c[5] * hy1.y));
    __half2 p3 = __float22half2_rn(make_float2(c[6] * hy1.z, c[7] * hy1.w));
    uint4 ov = { *reinterpret_cast<uint32_t*>(&p0), *reinterpret_cast<uint32_t*>(&p1),
                 *reinterpret_cast<uint32_t*>(&p2), *reinterpret_cast<uint32_t*>(&p3) };
    const size_t cb = ((size_t)b * Ssz + i) * Dsz + h * DKsz + dg * 8;
    *reinterpret_cast<uint4*>(ctxh + cb) = ov;
}

// ---------------------------------------------------------------------------
// LayerNorm: one warp per row, no smem, no barriers. 256 thr = 8 rows/blk.
// ---------------------------------------------------------------------------
__global__ __launch_bounds__(256) void ln2(
    const float* __restrict__ x, const float* __restrict__ gam,
    const float* __restrict__ bet, float* __restrict__ out)
{
    const int row = blockIdx.x * 8 + (threadIdx.x >> 5);
    const int lane = threadIdx.x & 31;
    const float4* xr = (const float4*)(x + (size_t)row * Dsz);

    float4 v[4];
    float s = 0.f, ss = 0.f;
#pragma unroll
    for (int t = 0; t < 4; t++) {
        v[t] = xr[lane + t * 32];
        s  += v[t].x + v[t].y + v[t].z + v[t].w;
        ss += v[t].x * v[t].x + v[t].y * v[t].y + v[t].z * v[t].z + v[t].w * v[t].w;
    }
#pragma unroll
    for (int off = 16; off > 0; off >>= 1) {
        s  += __shfl_xor_sync(0xFFFFFFFFu, s,  off);
        ss += __shfl_xor_sync(0xFFFFFFFFu, ss, off);
    }
    const float mu  = s * (1.f / Dsz);
    const float var = ss * (1.f / Dsz) - mu * mu;
    const float rstd = rsqrtf(var + 1e-5f);

    const float4* g4 = (const float4*)gam;
    const float4* b4 = (const float4*)bet;
    float4* o4 = (float4*)(out + (size_t)row * Dsz);
#pragma unroll
    for (int t = 0; t < 4; t++) {
        const float4 g = g4[lane + t * 32];
        const float4 bb = b4[lane + t * 32];
        float4 o;
        o.x = (v[t].x - mu) * rstd * g.x + bb.x;
        o.y = (v[t].y - mu) * rstd * g.y + bb.y;
        o.z = (v[t].z - mu) * rstd * g.z + bb.z;
        o.w = (v[t].w - mu) * rstd * g.w + bb.w;
        o4[lane + t * 32] = o;
    }
}

// ---------------------------------------------------------------------------
extern "C" void kernel_launch(void* const* d_in, const int* in_sizes, int n_in,
                              void* d_out, int out_size)
{
    const float* Q     = (const float*)d_in[0];
    const float* K     = (const float*)d_in[1];
    const float* V     = (const float*)d_in[2];
    const unsigned int* mask = (const unsigned int*)d_in[3];
    const float* hyper = (const float*)d_in[4];
    const float* Wq    = (const float*)d_in[5];
    const float* bq    = (const float*)d_in[6];
    const float* Wk    = (const float*)d_in[7];
    const float* bk    = (const float*)d_in[8];
    const float* Wv    = (const float*)d_in[9];
    const float* bv    = (const float*)d_in[10];
    const float* Wo    = (const float*)d_in[11];
    const float* bo    = (const float*)d_in[12];
    const float* ln_g  = (const float*)d_in[13];
    const float* ln_b  = (const float*)d_in[14];

    float* outp = (float*)d_out;
    float* wout = outp + OUT_ELEMS;

    float *pq, *pk, *pv, *plin;
    __half *pqh, *pkh, *pvh, *pctxh, *pwqh, *pwkh, *pwvh, *pwoh;
    cudaGetSymbolAddress((void**)&pq,    g_q);
    cudaGetSymbolAddress((void**)&pk,    g_k);
    cudaGetSymbolAddress((void**)&pv,    g_v);
    cudaGetSymbolAddress((void**)&plin,  g_lin);
    cudaGetSymbolAddress((void**)&pqh,   g_qh);
    cudaGetSymbolAddress((void**)&pkh,   g_kh);
    cudaGetSymbolAddress((void**)&pvh,   g_vh);
    cudaGetSymbolAddress((void**)&pctxh, g_ctxh);
    cudaGetSymbolAddress((void**)&pwqh,  g_wqh);
    cudaGetSymbolAddress((void**)&pwkh,  g_wkh);
    cudaGetSymbolAddress((void**)&pwvh,  g_wvh);
    cudaGetSymbolAddress((void**)&pwoh,  g_woh);

    cudaFuncSetAttribute(gemm_qkv, cudaFuncAttributeMaxDynamicSharedMemorySize, SMEM_SZ);
    cudaFuncSetAttribute(gemm_one, cudaFuncAttributeMaxDynamicSharedMemorySize, SMEM_SZ);

    conv_fp16<<<(CONV_TOTAL + 255) / 256, 256>>>(Q, K, V, Wq, Wk, Wv, Wo,
                                                 pqh, pkh, pvh, pwqh, pwkh, pwvh, pwoh);

    dim3 gq3(Dsz / BN, MTOT / BM, 3);   // (4, 64, 3) = 768 CTAs
    gemm_qkv<<<gq3, 512, SMEM_SZ>>>(pqh, pwqh, bq, pq,
                                    pkh, pwkh, bk, pk,
                                    pvh, pwvh, bv, pv);

    dim3 agrid(Bsz, Hsz / 8);           // (1024, 2)
    attn3<<<agrid, 256>>>(pq, pk, pv, mask, hyper, wout, pctxh);

    dim3 gg(Dsz / BN, MTOT / BM);       // (4, 64)
    gemm_one<<<gg, 512, SMEM_SZ>>>(pctxh, pwoh, bo, Q, plin);

    ln2<<<MTOT / 8, 256>>>(plin, ln_g, ln_b, outp);
}